// round 4
// baseline (speedup 1.0000x reference)
#include <cuda_runtime.h>
#include <cuda_bf16.h>
#include <stdint.h>

#define Sn 2048
#define Dn 64
#define Hn 16
#define BHn 64

static const size_t OSZ = (size_t)BHn * Sn * Dn;
#define EXP_SCALE 0.1803368801111204f   // 0.125 * log2(e)

// per-(bh, ktile, qrow) partial sums of exp-scores: 64*16*2048 floats = 8MB
__device__ float g_partials[BHn * 16 * Sn];

// ------------------------------------------------------------------ helpers
__device__ __forceinline__ uint32_t smem_u32(const void* p) {
    uint32_t a;
    asm("{ .reg .u64 t; cvta.to.shared.u64 t, %1; cvt.u32.u64 %0, t; }"
        : "=r"(a) : "l"(p));
    return a;
}

#define SW128(o) ((uint32_t)(o) ^ ((((uint32_t)(o)) >> 3) & 0x70))

__device__ __forceinline__ void ldsm_x4(uint32_t r[4], uint32_t addr) {
    asm volatile("ldmatrix.sync.aligned.m8n8.x4.shared.b16 {%0,%1,%2,%3}, [%4];"
                 : "=r"(r[0]), "=r"(r[1]), "=r"(r[2]), "=r"(r[3]) : "r"(addr));
}
__device__ __forceinline__ void ldsm_x4t(uint32_t r[4], uint32_t addr) {
    asm volatile("ldmatrix.sync.aligned.m8n8.x4.trans.shared.b16 {%0,%1,%2,%3}, [%4];"
                 : "=r"(r[0]), "=r"(r[1]), "=r"(r[2]), "=r"(r[3]) : "r"(addr));
}

__device__ __forceinline__ void mma16816(float c[4], const uint32_t a[4],
                                         uint32_t b0, uint32_t b1) {
    asm volatile(
        "mma.sync.aligned.m16n8k16.row.col.f32.bf16.bf16.f32 "
        "{%0,%1,%2,%3}, {%4,%5,%6,%7}, {%8,%9}, {%0,%1,%2,%3};"
        : "+f"(c[0]), "+f"(c[1]), "+f"(c[2]), "+f"(c[3])
        : "r"(a[0]), "r"(a[1]), "r"(a[2]), "r"(a[3]), "r"(b0), "r"(b1));
}

__device__ __forceinline__ void cvt_split(float x, uint16_t& h, uint16_t& l) {
    __nv_bfloat16 hb = __float2bfloat16_rn(x);
    float r = x - __bfloat162float(hb);
    __nv_bfloat16 lb = __float2bfloat16_rn(r);
    h = __bfloat16_as_ushort(hb);
    l = __bfloat16_as_ushort(lb);
}

__device__ __forceinline__ void store_split4(char* smem_hi, char* smem_lo,
                                             uint32_t sw, float4 v) {
    uint16_t h0, l0, h1, l1, h2, l2, h3, l3;
    cvt_split(v.x, h0, l0); cvt_split(v.y, h1, l1);
    cvt_split(v.z, h2, l2); cvt_split(v.w, h3, l3);
    uint2 hw, lw;
    hw.x = (uint32_t)h0 | ((uint32_t)h1 << 16);
    hw.y = (uint32_t)h2 | ((uint32_t)h3 << 16);
    lw.x = (uint32_t)l0 | ((uint32_t)l1 << 16);
    lw.y = (uint32_t)l2 | ((uint32_t)l3 << 16);
    *(uint2*)(smem_hi + sw) = hw;
    *(uint2*)(smem_lo + sw) = lw;
}

// ---------------------------------------------------------------------------
// Kernel 1: e = mask ? 0 : exp(Q@K^T * 0.125)  -> W;  row partial sums -> scratch
// Tile 128(q) x 128(k), 256 threads = 8 warps (4x2), warp tile 32x64.
// ---------------------------------------------------------------------------
__global__ void __launch_bounds__(256)
qk_kernel(const float* __restrict__ Q, const float* __restrict__ K,
          const int* __restrict__ mask, float* __restrict__ W) {
    extern __shared__ char smem[];
    const uint32_t sb = smem_u32(smem);
    const int tid = threadIdx.x, lid = tid & 31, wid = tid >> 5;
    const int warp_m = wid & 3, warp_n = wid >> 2;
    const int q0 = blockIdx.x * 128, k0 = blockIdx.y * 128, bh = blockIdx.z;
    const int b = bh / Hn;

    char* AH = smem;
    char* AL = smem + 16384;
    char* KH = smem + 32768;
    char* KL = smem + 49152;
    int*  mskS = (int*)(smem + 65536);
    float* psS = (float*)(smem + 65536 + 512);   // [2][128] per-warp_n row sums

    if (tid < 128) mskS[tid] = mask[b * Sn + k0 + tid];

    const float4* Qt = (const float4*)(Q + ((size_t)bh * Sn + q0) * Dn);
    const float4* Kt = (const float4*)(K + ((size_t)bh * Sn + k0) * Dn);
    #pragma unroll
    for (int j = 0; j < 8; j++) {
        const int f = tid + j * 256;
        const uint32_t sw = SW128((f >> 4) * 128 + (f & 15) * 8);
        store_split4(AH, AL, sw, Qt[f]);
        store_split4(KH, KL, sw, Kt[f]);
    }
    __syncthreads();

    float acc[16][4];
    #pragma unroll
    for (int i = 0; i < 16; i++)
        #pragma unroll
        for (int j = 0; j < 4; j++) acc[i][j] = 0.0f;

    #pragma unroll
    for (int ks = 0; ks < 4; ks++) {
        uint32_t aH[2][4], aL[2][4];
        #pragma unroll
        for (int mt = 0; mt < 2; mt++) {
            const uint32_t off = (uint32_t)(warp_m * 32 + mt * 16 + (lid & 15)) * 128
                               + ks * 32 + (lid >> 4) * 16;
            ldsm_x4(aH[mt], sb + SW128(off));
            ldsm_x4(aL[mt], sb + 16384 + SW128(off));
        }
        #pragma unroll
        for (int ng = 0; ng < 4; ng++) {
            const uint32_t boff = (uint32_t)(warp_n * 64 + ng * 16 + (lid & 15)) * 128
                                + ks * 32 + (lid >> 4) * 16;
            uint32_t bHf[4], bLf[4];
            ldsm_x4(bHf, sb + 32768 + SW128(boff));
            ldsm_x4(bLf, sb + 49152 + SW128(boff));
            #pragma unroll
            for (int mt = 0; mt < 2; mt++) {
                float* c0 = acc[mt * 8 + ng * 2 + 0];
                float* c1 = acc[mt * 8 + ng * 2 + 1];
                mma16816(c0, aH[mt], bHf[0], bHf[2]);
                mma16816(c0, aL[mt], bHf[0], bHf[2]);
                mma16816(c0, aH[mt], bLf[0], bLf[2]);
                mma16816(c1, aH[mt], bHf[1], bHf[3]);
                mma16816(c1, aL[mt], bHf[1], bHf[3]);
                mma16816(c1, aH[mt], bLf[1], bLf[3]);
            }
        }
    }

    // Epilogue: exp + mask -> e, store; accumulate row sums
    float* Wb = W + (size_t)bh * Sn * Sn;
    float rsum[2][2] = {{0.f, 0.f}, {0.f, 0.f}};   // [mt][row / row+8]
    #pragma unroll
    for (int mt = 0; mt < 2; mt++) {
        #pragma unroll
        for (int nt = 0; nt < 8; nt++) {
            const float* c = acc[mt * 8 + nt];
            const int row = q0 + warp_m * 32 + mt * 16 + (lid >> 2);
            const int colL = warp_n * 64 + nt * 8 + (lid & 3) * 2;
            const int m0 = mskS[colL], m1 = mskS[colL + 1];
            float e0 = m0 ? 0.f : exp2f(c[0] * EXP_SCALE);
            float e1 = m1 ? 0.f : exp2f(c[1] * EXP_SCALE);
            float e2 = m0 ? 0.f : exp2f(c[2] * EXP_SCALE);
            float e3 = m1 ? 0.f : exp2f(c[3] * EXP_SCALE);
            *(float2*)(Wb + (size_t)row * Sn + k0 + colL) = make_float2(e0, e1);
            *(float2*)(Wb + (size_t)(row + 8) * Sn + k0 + colL) = make_float2(e2, e3);
            rsum[mt][0] += e0 + e1;
            rsum[mt][1] += e2 + e3;
        }
    }
    // quad reduce (lanes lid&3 hold different cols of the same rows)
    #pragma unroll
    for (int off = 1; off < 4; off <<= 1) {
        #pragma unroll
        for (int mt = 0; mt < 2; mt++) {
            rsum[mt][0] += __shfl_xor_sync(0xffffffffu, rsum[mt][0], off);
            rsum[mt][1] += __shfl_xor_sync(0xffffffffu, rsum[mt][1], off);
        }
    }
    if ((lid & 3) == 0) {
        const int rbase = warp_m * 32 + (lid >> 2);
        #pragma unroll
        for (int mt = 0; mt < 2; mt++) {
            psS[warp_n * 128 + rbase + mt * 16]     = rsum[mt][0];
            psS[warp_n * 128 + rbase + mt * 16 + 8] = rsum[mt][1];
        }
    }
    __syncthreads();
    if (tid < 128) {
        g_partials[((size_t)bh * 16 + blockIdx.y) * Sn + q0 + tid]
            = psS[tid] + psS[128 + tid];
    }
}

// ---------------------------------------------------------------------------
// Kernel 2: O = (e @ V) * inv_l; also W <- e * inv_l (final attn_weights).
// Tile 128(q) x 64(d), k-loop 32 chunks of 64. 256 threads, warp tile 32x32.
// ---------------------------------------------------------------------------
__global__ void __launch_bounds__(256)
av_kernel(float* __restrict__ P, const float* __restrict__ V,
          float* __restrict__ O) {
    extern __shared__ char smem[];
    const uint32_t sb = smem_u32(smem);
    const int tid = threadIdx.x, lid = tid & 31, wid = tid >> 5;
    const int warp_m = wid & 3, warp_n = wid >> 2;
    const int q0 = blockIdx.x * 128, bh = blockIdx.y;

    char* PH = smem;
    char* PL = smem + 16384;
    char* VH = smem + 32768;
    char* VL = smem + 40960;
    float* invl = (float*)(smem + 49152);   // [128]

    if (tid < 128) {
        float l = 0.f;
        #pragma unroll
        for (int kt = 0; kt < 16; kt++)
            l += g_partials[((size_t)bh * 16 + kt) * Sn + q0 + tid];
        invl[tid] = 1.0f / l;
    }

    float* Pb = P + (size_t)bh * Sn * Sn + (size_t)q0 * Sn;
    const float* Vb = V + (size_t)bh * Sn * Dn;

    float acc[8][4];
    #pragma unroll
    for (int i = 0; i < 8; i++)
        #pragma unroll
        for (int j = 0; j < 4; j++) acc[i][j] = 0.0f;

    __syncthreads();   // invl ready

    for (int kc = 0; kc < Sn; kc += 64) {
        #pragma unroll
        for (int j = 0; j < 8; j++) {        // P tile 128x64: read e, write w
            const int f = tid + j * 256;
            const int row = f >> 4, colf = (f & 15) * 4;
            float4 v = *(const float4*)(Pb + (size_t)row * Sn + kc + colf);
            const float il = invl[row];
            v.x *= il; v.y *= il; v.z *= il; v.w *= il;
            *(float4*)(Pb + (size_t)row * Sn + kc + colf) = v;   // final weights
            store_split4(PH, PL, SW128(row * 128 + colf * 2), v);
        }
        #pragma unroll
        for (int j = 0; j < 4; j++) {        // V tile 64x64
            const int f = tid + j * 256;
            const int row = f >> 4, colf = (f & 15) * 4;
            float4 v = *(const float4*)(Vb + (size_t)(kc + row) * Dn + colf);
            store_split4(VH, VL, SW128(row * 128 + colf * 2), v);
        }
        __syncthreads();

        #pragma unroll
        for (int ks = 0; ks < 4; ks++) {
            uint32_t aH[2][4], aL[2][4];
            #pragma unroll
            for (int mt = 0; mt < 2; mt++) {
                const uint32_t off = (uint32_t)(warp_m * 32 + mt * 16 + (lid & 15)) * 128
                                   + ks * 32 + (lid >> 4) * 16;
                ldsm_x4(aH[mt], sb + SW128(off));
                ldsm_x4(aL[mt], sb + 16384 + SW128(off));
            }
            #pragma unroll
            for (int ng = 0; ng < 2; ng++) {
                const uint32_t voff =
                    (uint32_t)(ks * 16 + (lid & 7) + ((lid >> 3) & 1) * 8) * 128
                    + (warp_n * 32 + ng * 16 + (lid >> 4) * 8) * 2;
                uint32_t bHf[4], bLf[4];
                ldsm_x4t(bHf, sb + 32768 + SW128(voff));
                ldsm_x4t(bLf, sb + 40960 + SW128(voff));
                #pragma unroll
                for (int mt = 0; mt < 2; mt++) {
                    float* c0 = acc[mt * 4 + ng * 2 + 0];
                    float* c1 = acc[mt * 4 + ng * 2 + 1];
                    mma16816(c0, aH[mt], bHf[0], bHf[1]);
                    mma16816(c0, aL[mt], bHf[0], bHf[1]);
                    mma16816(c0, aH[mt], bLf[0], bLf[1]);
                    mma16816(c1, aH[mt], bHf[2], bHf[3]);
                    mma16816(c1, aL[mt], bHf[2], bHf[3]);
                    mma16816(c1, aH[mt], bLf[2], bLf[3]);
                }
            }
        }
        __syncthreads();
    }

    float* Ob = O + ((size_t)bh * Sn + q0) * Dn;
    #pragma unroll
    for (int mt = 0; mt < 2; mt++) {
        #pragma unroll
        for (int nt = 0; nt < 4; nt++) {
            const float* c = acc[mt * 4 + nt];
            const int row = warp_m * 32 + mt * 16 + (lid >> 2);
            const int col = warp_n * 32 + nt * 8 + (lid & 3) * 2;
            *(float2*)(Ob + (size_t)row * Dn + col) = make_float2(c[0], c[1]);
            *(float2*)(Ob + (size_t)(row + 8) * Dn + col) = make_float2(c[2], c[3]);
        }
    }
}

// ---------------------------------------------------------------------------
extern "C" void kernel_launch(void* const* d_in, const int* in_sizes, int n_in,
                              void* d_out, int out_size) {
    const float* Q    = (const float*)d_in[0];
    const float* K    = (const float*)d_in[1];
    const float* V    = (const float*)d_in[2];
    const int*   mask = (const int*)  d_in[3];

    float* O = (float*)d_out;
    float* W = O + OSZ;

    static const int QK_SMEM = 65536 + 512 + 1024;   // tiles + mask + partials
    static const int AV_SMEM = 49152 + 512;          // tiles + invl

    cudaFuncSetAttribute(qk_kernel, cudaFuncAttributeMaxDynamicSharedMemorySize, QK_SMEM);
    cudaFuncSetAttribute(av_kernel, cudaFuncAttributeMaxDynamicSharedMemorySize, AV_SMEM);

    {
        dim3 grid(Sn / 128, Sn / 128, BHn);
        qk_kernel<<<grid, 256, QK_SMEM>>>(Q, K, mask, W);
    }
    {
        dim3 grid(Sn / 128, BHn);
        av_kernel<<<grid, 256, AV_SMEM>>>(W, V, O);
    }
    (void)in_sizes; (void)n_in; (void)out_size;
}

// round 5
// speedup vs baseline: 1.4534x; 1.4534x over previous
#include <cuda_runtime.h>
#include <cuda_bf16.h>
#include <stdint.h>

#define Sn 2048
#define Dn 64
#define Hn 16
#define BHn 64

static const size_t OSZ = (size_t)BHn * Sn * Dn;
#define EXP_SCALE 0.1803368801111204f   // 0.125 * log2(e)

// scratch: per-(bh, ktile, qrow) partial sums (8MB) + pre-split bf16 Q/K/V (100MB)
__device__ float g_partials[BHn * 16 * Sn];
__device__ __nv_bfloat16 gQH[(size_t)BHn * Sn * Dn];
__device__ __nv_bfloat16 gQL[(size_t)BHn * Sn * Dn];
__device__ __nv_bfloat16 gKH[(size_t)BHn * Sn * Dn];
__device__ __nv_bfloat16 gKL[(size_t)BHn * Sn * Dn];
__device__ __nv_bfloat16 gVH[(size_t)BHn * Sn * Dn];
__device__ __nv_bfloat16 gVL[(size_t)BHn * Sn * Dn];

// ------------------------------------------------------------------ helpers
__device__ __forceinline__ uint32_t smem_u32(const void* p) {
    uint32_t a;
    asm("{ .reg .u64 t; cvta.to.shared.u64 t, %1; cvt.u32.u64 %0, t; }"
        : "=r"(a) : "l"(p));
    return a;
}

#define SW128(o) ((uint32_t)(o) ^ ((((uint32_t)(o)) >> 3) & 0x70))

__device__ __forceinline__ float ex2f(float x) {
    float y; asm("ex2.approx.ftz.f32 %0, %1;" : "=f"(y) : "f"(x)); return y;
}

__device__ __forceinline__ void cpa16(uint32_t dst, const void* src) {
    asm volatile("cp.async.cg.shared.global [%0], [%1], 16;"
                 :: "r"(dst), "l"(src));
}
#define CPA_COMMIT() asm volatile("cp.async.commit_group;" ::: "memory")
#define CPA_WAIT(n)  asm volatile("cp.async.wait_group %0;" :: "n"(n) : "memory")

__device__ __forceinline__ void ldsm_x4(uint32_t r[4], uint32_t addr) {
    asm volatile("ldmatrix.sync.aligned.m8n8.x4.shared.b16 {%0,%1,%2,%3}, [%4];"
                 : "=r"(r[0]), "=r"(r[1]), "=r"(r[2]), "=r"(r[3]) : "r"(addr));
}
__device__ __forceinline__ void ldsm_x4t(uint32_t r[4], uint32_t addr) {
    asm volatile("ldmatrix.sync.aligned.m8n8.x4.trans.shared.b16 {%0,%1,%2,%3}, [%4];"
                 : "=r"(r[0]), "=r"(r[1]), "=r"(r[2]), "=r"(r[3]) : "r"(addr));
}

__device__ __forceinline__ void mma16816(float c[4], const uint32_t a[4],
                                         uint32_t b0, uint32_t b1) {
    asm volatile(
        "mma.sync.aligned.m16n8k16.row.col.f32.bf16.bf16.f32 "
        "{%0,%1,%2,%3}, {%4,%5,%6,%7}, {%8,%9}, {%0,%1,%2,%3};"
        : "+f"(c[0]), "+f"(c[1]), "+f"(c[2]), "+f"(c[3])
        : "r"(a[0]), "r"(a[1]), "r"(a[2]), "r"(a[3]), "r"(b0), "r"(b1));
}

__device__ __forceinline__ void cvt_split(float x, uint16_t& h, uint16_t& l) {
    __nv_bfloat16 hb = __float2bfloat16_rn(x);
    float r = x - __bfloat162float(hb);
    __nv_bfloat16 lb = __float2bfloat16_rn(r);
    h = __bfloat16_as_ushort(hb);
    l = __bfloat16_as_ushort(lb);
}

// ---------------------------------------------------------------------------
// Kernel 0: pre-split Q/K/V into bf16 hi/lo pairs.
// ---------------------------------------------------------------------------
__global__ void __launch_bounds__(256)
prep_kernel(const float* __restrict__ Q, const float* __restrict__ K,
            const float* __restrict__ V) {
    const float* src;
    __nv_bfloat16 *dh, *dl;
    if (blockIdx.y == 0)      { src = Q; dh = gQH; dl = gQL; }
    else if (blockIdx.y == 1) { src = K; dh = gKH; dl = gKL; }
    else                      { src = V; dh = gVH; dl = gVL; }

    const size_t i4 = (size_t)blockIdx.x * 256 + threadIdx.x;  // float4 index
    float4 v = ((const float4*)src)[i4];
    uint16_t h0, l0, h1, l1, h2, l2, h3, l3;
    cvt_split(v.x, h0, l0); cvt_split(v.y, h1, l1);
    cvt_split(v.z, h2, l2); cvt_split(v.w, h3, l3);
    uint2 hw, lw;
    hw.x = (uint32_t)h0 | ((uint32_t)h1 << 16);
    hw.y = (uint32_t)h2 | ((uint32_t)h3 << 16);
    lw.x = (uint32_t)l0 | ((uint32_t)l1 << 16);
    lw.y = (uint32_t)l2 | ((uint32_t)l3 << 16);
    ((uint2*)dh)[i4] = hw;
    ((uint2*)dl)[i4] = lw;
}

// ---------------------------------------------------------------------------
// Kernel 1: row partial sums of e = mask ? 0 : exp(Q@K^T / 8).  No W store.
// Tile 128(q) x 128(k). 256 threads = 8 warps (4x2), warp tile 32x64.
// ---------------------------------------------------------------------------
__global__ void __launch_bounds__(256)
sums_kernel(const int* __restrict__ mask) {
    extern __shared__ char smem[];
    const uint32_t sb = smem_u32(smem);
    const int tid = threadIdx.x, lid = tid & 31, wid = tid >> 5;
    const int warp_m = wid & 3, warp_n = wid >> 2;
    const int q0 = blockIdx.x * 128, k0 = blockIdx.y * 128, bh = blockIdx.z;
    const int b = bh >> 4;

    // smem: QH 0, QL 16384, KH 32768, KL 49152, msk 65536, ps 66048
    int*   mskS = (int*)(smem + 65536);
    float* psS  = (float*)(smem + 66048);

    // cp.async the 4 pre-split tiles (16KB each, 1024 x 16B chunks)
    #pragma unroll
    for (int j = 0; j < 4; j++) {
        const int f = tid + j * 256;
        const int row = f >> 3, c16 = f & 7;
        const uint32_t sw = SW128(row * 128 + c16 * 16);
        const size_t qsrc = ((size_t)bh * Sn + q0 + row) * Dn + c16 * 8;
        const size_t ksrc = ((size_t)bh * Sn + k0 + row) * Dn + c16 * 8;
        cpa16(sb + sw,         gQH + qsrc);
        cpa16(sb + 16384 + sw, gQL + qsrc);
        cpa16(sb + 32768 + sw, gKH + ksrc);
        cpa16(sb + 49152 + sw, gKL + ksrc);
    }
    CPA_COMMIT();
    if (tid < 128) mskS[tid] = mask[b * Sn + k0 + tid];
    CPA_WAIT(0);
    __syncthreads();

    float acc[16][4];
    #pragma unroll
    for (int i = 0; i < 16; i++)
        #pragma unroll
        for (int j = 0; j < 4; j++) acc[i][j] = 0.0f;

    #pragma unroll
    for (int ks = 0; ks < 4; ks++) {
        uint32_t aH[2][4], aL[2][4];
        #pragma unroll
        for (int mt = 0; mt < 2; mt++) {
            const uint32_t off = (uint32_t)(warp_m * 32 + mt * 16 + (lid & 15)) * 128
                               + ks * 32 + (lid >> 4) * 16;
            ldsm_x4(aH[mt], sb + SW128(off));
            ldsm_x4(aL[mt], sb + 16384 + SW128(off));
        }
        #pragma unroll
        for (int ng = 0; ng < 4; ng++) {
            const uint32_t boff = (uint32_t)(warp_n * 64 + ng * 16 + (lid & 15)) * 128
                                + ks * 32 + (lid >> 4) * 16;
            uint32_t bHf[4], bLf[4];
            ldsm_x4(bHf, sb + 32768 + SW128(boff));
            ldsm_x4(bLf, sb + 49152 + SW128(boff));
            #pragma unroll
            for (int mt = 0; mt < 2; mt++) {
                float* c0 = acc[mt * 8 + ng * 2 + 0];
                float* c1 = acc[mt * 8 + ng * 2 + 1];
                mma16816(c0, aH[mt], bHf[0], bHf[2]);
                mma16816(c0, aL[mt], bHf[0], bHf[2]);
                mma16816(c0, aH[mt], bLf[0], bLf[2]);
                mma16816(c1, aH[mt], bHf[1], bHf[3]);
                mma16816(c1, aL[mt], bHf[1], bHf[3]);
                mma16816(c1, aH[mt], bLf[1], bLf[3]);
            }
        }
    }

    float rsum[2][2] = {{0.f, 0.f}, {0.f, 0.f}};
    #pragma unroll
    for (int mt = 0; mt < 2; mt++) {
        #pragma unroll
        for (int nt = 0; nt < 8; nt++) {
            const float* c = acc[mt * 8 + nt];
            const int colL = warp_n * 64 + nt * 8 + (lid & 3) * 2;
            const int m0 = mskS[colL], m1 = mskS[colL + 1];
            float e0 = m0 ? 0.f : ex2f(c[0] * EXP_SCALE);
            float e1 = m1 ? 0.f : ex2f(c[1] * EXP_SCALE);
            float e2 = m0 ? 0.f : ex2f(c[2] * EXP_SCALE);
            float e3 = m1 ? 0.f : ex2f(c[3] * EXP_SCALE);
            rsum[mt][0] += e0 + e1;
            rsum[mt][1] += e2 + e3;
        }
    }
    #pragma unroll
    for (int off = 1; off < 4; off <<= 1) {
        #pragma unroll
        for (int mt = 0; mt < 2; mt++) {
            rsum[mt][0] += __shfl_xor_sync(0xffffffffu, rsum[mt][0], off);
            rsum[mt][1] += __shfl_xor_sync(0xffffffffu, rsum[mt][1], off);
        }
    }
    if ((lid & 3) == 0) {
        const int rbase = warp_m * 32 + (lid >> 2);
        #pragma unroll
        for (int mt = 0; mt < 2; mt++) {
            psS[warp_n * 128 + rbase + mt * 16]     = rsum[mt][0];
            psS[warp_n * 128 + rbase + mt * 16 + 8] = rsum[mt][1];
        }
    }
    __syncthreads();
    if (tid < 128) {
        g_partials[((size_t)bh * 16 + blockIdx.y) * Sn + q0 + tid]
            = psS[tid] + psS[128 + tid];
    }
}

// ---------------------------------------------------------------------------
// Kernel 2: fused. Per 128-q block: recompute S chunkwise, w = e*invl,
// write w (final weights) once, O += w @ V.  Double-buffered cp.async K,V.
// ---------------------------------------------------------------------------
// smem offsets
#define F_QH 0
#define F_QL 16384
#define F_PH 32768
#define F_PL 49152
#define F_K(s)  (65536 + (s) * 16384)        // KH at +0, KL at +8192
#define F_V(s)  (98304 + (s) * 16384)        // VH at +0, VL at +8192
#define F_MSK 131072
#define F_INVL 133120
#define F_TOTAL 133632

__global__ void __launch_bounds__(256)
fused_kernel(const int* __restrict__ mask, float* __restrict__ W,
             float* __restrict__ O) {
    extern __shared__ char smem[];
    const uint32_t sb = smem_u32(smem);
    const int tid = threadIdx.x, lid = tid & 31, wid = tid >> 5;
    const int warp_m = wid & 3, warp_n = wid >> 2;
    const int q0 = blockIdx.x * 128, bh = blockIdx.y;
    const int b = bh >> 4;

    char*  mskC = smem + F_MSK;
    float* invl = (float*)(smem + F_INVL);

    // --- prologue: Q tiles + chunk0 (group0), chunk1 (group1)
    #pragma unroll
    for (int j = 0; j < 4; j++) {
        const int f = tid + j * 256;
        const int row = f >> 3, c16 = f & 7;
        const uint32_t sw = SW128(row * 128 + c16 * 16);
        const size_t src = ((size_t)bh * Sn + q0 + row) * Dn + c16 * 8;
        cpa16(sb + F_QH + sw, gQH + src);
        cpa16(sb + F_QL + sw, gQL + src);
    }
    #pragma unroll
    for (int j = 0; j < 2; j++) {                    // chunk 0: K,V 64 rows
        const int f = tid + j * 256;
        const int row = f >> 3, c16 = f & 7;
        const uint32_t sw = SW128(row * 128 + c16 * 16);
        const size_t src = ((size_t)bh * Sn + row) * Dn + c16 * 8;
        cpa16(sb + F_K(0) + sw,        gKH + src);
        cpa16(sb + F_K(0) + 8192 + sw, gKL + src);
        cpa16(sb + F_V(0) + sw,        gVH + src);
        cpa16(sb + F_V(0) + 8192 + sw, gVL + src);
    }
    CPA_COMMIT();
    #pragma unroll
    for (int j = 0; j < 2; j++) {                    // chunk 1
        const int f = tid + j * 256;
        const int row = f >> 3, c16 = f & 7;
        const uint32_t sw = SW128(row * 128 + c16 * 16);
        const size_t src = ((size_t)bh * Sn + 64 + row) * Dn + c16 * 8;
        cpa16(sb + F_K(1) + sw,        gKH + src);
        cpa16(sb + F_K(1) + 8192 + sw, gKL + src);
        cpa16(sb + F_V(1) + sw,        gVH + src);
        cpa16(sb + F_V(1) + 8192 + sw, gVL + src);
    }
    CPA_COMMIT();

    #pragma unroll
    for (int j = 0; j < 8; j++) {
        const int i = tid + j * 256;
        mskC[i] = (char)mask[b * Sn + i];
    }
    if (tid < 128) {
        float l = 0.f;
        #pragma unroll
        for (int kt = 0; kt < 16; kt++)
            l += g_partials[((size_t)bh * 16 + kt) * Sn + q0 + tid];
        invl[tid] = 1.0f / l;
    }

    float accO[8][4];
    #pragma unroll
    for (int i = 0; i < 8; i++)
        #pragma unroll
        for (int j = 0; j < 4; j++) accO[i][j] = 0.0f;

    float* Wb = W + (size_t)bh * Sn * Sn;

    for (int it = 0; it < 32; it++) {
        const int s = it & 1;
        const int kc = it * 64;
        if (it == 31) { CPA_WAIT(0); } else { CPA_WAIT(1); }
        __syncthreads();

        // ---- QK: S = Q @ K_chunk^T  (128 x 64)
        float accS[8][4];
        #pragma unroll
        for (int i = 0; i < 8; i++)
            #pragma unroll
            for (int j = 0; j < 4; j++) accS[i][j] = 0.0f;

        #pragma unroll
        for (int ks = 0; ks < 4; ks++) {
            uint32_t aH[2][4], aL[2][4];
            #pragma unroll
            for (int mt = 0; mt < 2; mt++) {
                const uint32_t off = (uint32_t)(warp_m * 32 + mt * 16 + (lid & 15)) * 128
                                   + ks * 32 + (lid >> 4) * 16;
                ldsm_x4(aH[mt], sb + F_QH + SW128(off));
                ldsm_x4(aL[mt], sb + F_QL + SW128(off));
            }
            #pragma unroll
            for (int ng = 0; ng < 2; ng++) {
                const uint32_t boff = (uint32_t)(warp_n * 32 + ng * 16 + (lid & 15)) * 128
                                    + ks * 32 + (lid >> 4) * 16;
                uint32_t bHf[4], bLf[4];
                ldsm_x4(bHf, sb + F_K(s) + SW128(boff));
                ldsm_x4(bLf, sb + F_K(s) + 8192 + SW128(boff));
                #pragma unroll
                for (int mt = 0; mt < 2; mt++) {
                    float* c0 = accS[mt * 4 + ng * 2 + 0];
                    float* c1 = accS[mt * 4 + ng * 2 + 1];
                    mma16816(c0, aH[mt], bHf[0], bHf[2]);
                    mma16816(c0, aL[mt], bHf[0], bHf[2]);
                    mma16816(c0, aH[mt], bLf[0], bLf[2]);
                    mma16816(c1, aH[mt], bHf[1], bHf[3]);
                    mma16816(c1, aL[mt], bHf[1], bHf[3]);
                    mma16816(c1, aH[mt], bLf[1], bLf[3]);
                }
            }
        }

        // ---- epilogue: e, w = e*invl, write w, split w -> PH/PL
        #pragma unroll
        for (int mt = 0; mt < 2; mt++) {
            const int rl0 = warp_m * 32 + mt * 16 + (lid >> 2);
            const int rl1 = rl0 + 8;
            const float il0 = invl[rl0], il1 = invl[rl1];
            #pragma unroll
            for (int nt = 0; nt < 4; nt++) {
                const float* c = accS[mt * 4 + nt];
                const int col = warp_n * 32 + nt * 8 + (lid & 3) * 2;
                const int kg = kc + col;
                const int m0 = mskC[kg], m1 = mskC[kg + 1];
                const float e0 = m0 ? 0.f : ex2f(c[0] * EXP_SCALE);
                const float e1 = m1 ? 0.f : ex2f(c[1] * EXP_SCALE);
                const float e2 = m0 ? 0.f : ex2f(c[2] * EXP_SCALE);
                const float e3 = m1 ? 0.f : ex2f(c[3] * EXP_SCALE);
                const float w0 = e0 * il0, w1 = e1 * il0;
                const float w2 = e2 * il1, w3 = e3 * il1;
                *(float2*)(Wb + (size_t)(q0 + rl0) * Sn + kg) = make_float2(w0, w1);
                *(float2*)(Wb + (size_t)(q0 + rl1) * Sn + kg) = make_float2(w2, w3);
                uint16_t h0, l0, h1, l1;
                cvt_split(w0, h0, l0); cvt_split(w1, h1, l1);
                const uint32_t sw0 = SW128((uint32_t)(rl0 * 128 + col * 2));
                *(uint32_t*)(smem + F_PH + sw0) = (uint32_t)h0 | ((uint32_t)h1 << 16);
                *(uint32_t*)(smem + F_PL + sw0) = (uint32_t)l0 | ((uint32_t)l1 << 16);
                cvt_split(w2, h0, l0); cvt_split(w3, h1, l1);
                const uint32_t sw1 = SW128((uint32_t)(rl1 * 128 + col * 2));
                *(uint32_t*)(smem + F_PH + sw1) = (uint32_t)h0 | ((uint32_t)h1 << 16);
                *(uint32_t*)(smem + F_PL + sw1) = (uint32_t)l0 | ((uint32_t)l1 << 16);
            }
        }
        __syncthreads();

        // ---- AV: O += P @ V_chunk  (128 x 64)
        #pragma unroll
        for (int ks = 0; ks < 4; ks++) {
            uint32_t aH[2][4], aL[2][4];
            #pragma unroll
            for (int mt = 0; mt < 2; mt++) {
                const uint32_t off = (uint32_t)(warp_m * 32 + mt * 16 + (lid & 15)) * 128
                                   + ks * 32 + (lid >> 4) * 16;
                ldsm_x4(aH[mt], sb + F_PH + SW128(off));
                ldsm_x4(aL[mt], sb + F_PL + SW128(off));
            }
            #pragma unroll
            for (int ng = 0; ng < 2; ng++) {
                const uint32_t voff =
                    (uint32_t)(ks * 16 + (lid & 7) + ((lid >> 3) & 1) * 8) * 128
                    + (warp_n * 32 + ng * 16 + (lid >> 4) * 8) * 2;
                uint32_t bHf[4], bLf[4];
                ldsm_x4t(bHf, sb + F_V(s) + SW128(voff));
                ldsm_x4t(bLf, sb + F_V(s) + 8192 + SW128(voff));
                #pragma unroll
                for (int mt = 0; mt < 2; mt++) {
                    float* c0 = accO[mt * 4 + ng * 2 + 0];
                    float* c1 = accO[mt * 4 + ng * 2 + 1];
                    mma16816(c0, aH[mt], bHf[0], bHf[1]);
                    mma16816(c0, aL[mt], bHf[0], bHf[1]);
                    mma16816(c0, aH[mt], bLf[0], bLf[1]);
                    mma16816(c1, aH[mt], bHf[2], bHf[3]);
                    mma16816(c1, aL[mt], bHf[2], bHf[3]);
                    mma16816(c1, aH[mt], bLf[2], bLf[3]);
                }
            }
        }
        __syncthreads();   // all reads of stage s done before refill

        if (it + 2 < 32) {
            const int kn = (it + 2) * 64;
            #pragma unroll
            for (int j = 0; j < 2; j++) {
                const int f = tid + j * 256;
                const int row = f >> 3, c16 = f & 7;
                const uint32_t sw = SW128(row * 128 + c16 * 16);
                const size_t src = ((size_t)bh * Sn + kn + row) * Dn + c16 * 8;
                cpa16(sb + F_K(s) + sw,        gKH + src);
                cpa16(sb + F_K(s) + 8192 + sw, gKL + src);
                cpa16(sb + F_V(s) + sw,        gVH + src);
                cpa16(sb + F_V(s) + 8192 + sw, gVL + src);
            }
            CPA_COMMIT();
        }
    }

    float* Ob = O + ((size_t)bh * Sn + q0) * Dn;
    #pragma unroll
    for (int mt = 0; mt < 2; mt++) {
        #pragma unroll
        for (int nt = 0; nt < 4; nt++) {
            const float* c = accO[mt * 4 + nt];
            const int row = warp_m * 32 + mt * 16 + (lid >> 2);
            const int col = warp_n * 32 + nt * 8 + (lid & 3) * 2;
            *(float2*)(Ob + (size_t)row * Dn + col) = make_float2(c[0], c[1]);
            *(float2*)(Ob + (size_t)(row + 8) * Dn + col) = make_float2(c[2], c[3]);
        }
    }
}

// ---------------------------------------------------------------------------
extern "C" void kernel_launch(void* const* d_in, const int* in_sizes, int n_in,
                              void* d_out, int out_size) {
    const float* Q    = (const float*)d_in[0];
    const float* K    = (const float*)d_in[1];
    const float* V    = (const float*)d_in[2];
    const int*   mask = (const int*)  d_in[3];

    float* O = (float*)d_out;
    float* W = O + OSZ;

    static const int SUMS_SMEM = 65536 + 512 + 1024;

    cudaFuncSetAttribute(sums_kernel, cudaFuncAttributeMaxDynamicSharedMemorySize, SUMS_SMEM);
    cudaFuncSetAttribute(fused_kernel, cudaFuncAttributeMaxDynamicSharedMemorySize, F_TOTAL);

    {
        dim3 grid((unsigned)(OSZ / 4 / 256), 3);
        prep_kernel<<<grid, 256>>>(Q, K, V);
    }
    {
        dim3 grid(Sn / 128, Sn / 128, BHn);
        sums_kernel<<<grid, 256, SUMS_SMEM>>>(mask);
    }
    {
        dim3 grid(Sn / 128, BHn);
        fused_kernel<<<grid, 256, F_TOTAL>>>(mask, W, O);
    }
    (void)in_sizes; (void)n_in; (void)out_size;
}

// round 6
// speedup vs baseline: 2.0033x; 1.3783x over previous
#include <cuda_runtime.h>
#include <cuda_bf16.h>
#include <cuda_fp16.h>
#include <stdint.h>

#define Sn 2048
#define Dn 64
#define Hn 16
#define BHn 64

static const size_t OSZ = (size_t)BHn * Sn * Dn;
#define EXP_SCALE 0.1803368801111204f   // 0.125 * log2(e)

// scratch: partial sums (8MB) + fp16 Q/K (32MB) + bf16 hi/lo V (32MB)
__device__ float g_partials[BHn * 16 * Sn];
__device__ __half gQf[(size_t)BHn * Sn * Dn];
__device__ __half gKf[(size_t)BHn * Sn * Dn];
__device__ __nv_bfloat16 gVH[(size_t)BHn * Sn * Dn];
__device__ __nv_bfloat16 gVL[(size_t)BHn * Sn * Dn];

// ------------------------------------------------------------------ helpers
__device__ __forceinline__ uint32_t smem_u32(const void* p) {
    uint32_t a;
    asm("{ .reg .u64 t; cvta.to.shared.u64 t, %1; cvt.u32.u64 %0, t; }"
        : "=r"(a) : "l"(p));
    return a;
}

#define SW128(o) ((uint32_t)(o) ^ ((((uint32_t)(o)) >> 3) & 0x70))

__device__ __forceinline__ float ex2f(float x) {
    float y; asm("ex2.approx.ftz.f32 %0, %1;" : "=f"(y) : "f"(x)); return y;
}

__device__ __forceinline__ void cpa16(uint32_t dst, const void* src) {
    asm volatile("cp.async.cg.shared.global [%0], [%1], 16;"
                 :: "r"(dst), "l"(src));
}
#define CPA_COMMIT() asm volatile("cp.async.commit_group;" ::: "memory")
#define CPA_WAIT(n)  asm volatile("cp.async.wait_group %0;" :: "n"(n) : "memory")

__device__ __forceinline__ void ldsm_x4(uint32_t r[4], uint32_t addr) {
    asm volatile("ldmatrix.sync.aligned.m8n8.x4.shared.b16 {%0,%1,%2,%3}, [%4];"
                 : "=r"(r[0]), "=r"(r[1]), "=r"(r[2]), "=r"(r[3]) : "r"(addr));
}
__device__ __forceinline__ void ldsm_x4t(uint32_t r[4], uint32_t addr) {
    asm volatile("ldmatrix.sync.aligned.m8n8.x4.trans.shared.b16 {%0,%1,%2,%3}, [%4];"
                 : "=r"(r[0]), "=r"(r[1]), "=r"(r[2]), "=r"(r[3]) : "r"(addr));
}

__device__ __forceinline__ void mma16816(float c[4], const uint32_t a[4],
                                         uint32_t b0, uint32_t b1) {
    asm volatile(
        "mma.sync.aligned.m16n8k16.row.col.f32.bf16.bf16.f32 "
        "{%0,%1,%2,%3}, {%4,%5,%6,%7}, {%8,%9}, {%0,%1,%2,%3};"
        : "+f"(c[0]), "+f"(c[1]), "+f"(c[2]), "+f"(c[3])
        : "r"(a[0]), "r"(a[1]), "r"(a[2]), "r"(a[3]), "r"(b0), "r"(b1));
}
__device__ __forceinline__ void mma16816h(float c[4], const uint32_t a[4],
                                          uint32_t b0, uint32_t b1) {
    asm volatile(
        "mma.sync.aligned.m16n8k16.row.col.f32.f16.f16.f32 "
        "{%0,%1,%2,%3}, {%4,%5,%6,%7}, {%8,%9}, {%0,%1,%2,%3};"
        : "+f"(c[0]), "+f"(c[1]), "+f"(c[2]), "+f"(c[3])
        : "r"(a[0]), "r"(a[1]), "r"(a[2]), "r"(a[3]), "r"(b0), "r"(b1));
}

__device__ __forceinline__ void cvt_split(float x, uint16_t& h, uint16_t& l) {
    __nv_bfloat16 hb = __float2bfloat16_rn(x);
    float r = x - __bfloat162float(hb);
    __nv_bfloat16 lb = __float2bfloat16_rn(r);
    h = __bfloat16_as_ushort(hb);
    l = __bfloat16_as_ushort(lb);
}

__device__ __forceinline__ uint32_t pack_h2(float a, float b) {
    __half2 h = __floats2half2_rn(a, b);
    return *(uint32_t*)&h;
}

// ---------------------------------------------------------------------------
// Kernel 0: Q,K -> fp16; V -> bf16 hi/lo.
// ---------------------------------------------------------------------------
__global__ void __launch_bounds__(256)
prep_kernel(const float* __restrict__ Q, const float* __restrict__ K,
            const float* __restrict__ V) {
    const size_t i4 = (size_t)blockIdx.x * 256 + threadIdx.x;  // float4 index
    const int y = blockIdx.y;
    if (y < 2) {
        const float* src = y ? K : Q;
        __half* dst = y ? gKf : gQf;
        float4 v = ((const float4*)src)[i4];
        uint2 o;
        o.x = pack_h2(v.x, v.y);
        o.y = pack_h2(v.z, v.w);
        ((uint2*)dst)[i4] = o;
    } else {
        float4 v = ((const float4*)V)[i4];
        uint16_t h0, l0, h1, l1, h2, l2, h3, l3;
        cvt_split(v.x, h0, l0); cvt_split(v.y, h1, l1);
        cvt_split(v.z, h2, l2); cvt_split(v.w, h3, l3);
        uint2 hw, lw;
        hw.x = (uint32_t)h0 | ((uint32_t)h1 << 16);
        hw.y = (uint32_t)h2 | ((uint32_t)h3 << 16);
        lw.x = (uint32_t)l0 | ((uint32_t)l1 << 16);
        lw.y = (uint32_t)l2 | ((uint32_t)l3 << 16);
        ((uint2*)gVH)[i4] = hw;
        ((uint2*)gVL)[i4] = lw;
    }
}

// ---------------------------------------------------------------------------
// Kernel 1: row partial sums of e = mask ? 0 : exp(Q@K^T / 8).  fp16 QK.
// Tile 128(q) x 128(k). 256 threads = 8 warps (4x2), warp tile 32x64.
// ---------------------------------------------------------------------------
__global__ void __launch_bounds__(256)
sums_kernel(const int* __restrict__ mask) {
    extern __shared__ char smem[];
    const uint32_t sb = smem_u32(smem);
    const int tid = threadIdx.x, lid = tid & 31, wid = tid >> 5;
    const int warp_m = wid & 3, warp_n = wid >> 2;
    const int q0 = blockIdx.x * 128, k0 = blockIdx.y * 128, bh = blockIdx.z;
    const int b = bh >> 4;

    // smem: Qf @0 (16KB), Kf @16384 (16KB), msk @32768, ps @33280
    int*   mskS = (int*)(smem + 32768);
    float* psS  = (float*)(smem + 33280);

    #pragma unroll
    for (int j = 0; j < 4; j++) {
        const int f = tid + j * 256;                 // 1024 chunks of 16B
        const int row = f >> 3, c16 = f & 7;
        const uint32_t sw = SW128(row * 128 + c16 * 16);
        const size_t qsrc = ((size_t)bh * Sn + q0 + row) * Dn + c16 * 8;
        const size_t ksrc = ((size_t)bh * Sn + k0 + row) * Dn + c16 * 8;
        cpa16(sb + sw,         gQf + qsrc);
        cpa16(sb + 16384 + sw, gKf + ksrc);
    }
    CPA_COMMIT();
    if (tid < 128) mskS[tid] = mask[b * Sn + k0 + tid];
    CPA_WAIT(0);
    __syncthreads();

    float acc[16][4];
    #pragma unroll
    for (int i = 0; i < 16; i++)
        #pragma unroll
        for (int j = 0; j < 4; j++) acc[i][j] = 0.0f;

    #pragma unroll
    for (int ks = 0; ks < 4; ks++) {
        uint32_t aF[2][4];
        #pragma unroll
        for (int mt = 0; mt < 2; mt++) {
            const uint32_t off = (uint32_t)(warp_m * 32 + mt * 16 + (lid & 15)) * 128
                               + ks * 32 + (lid >> 4) * 16;
            ldsm_x4(aF[mt], sb + SW128(off));
        }
        #pragma unroll
        for (int ng = 0; ng < 4; ng++) {
            const uint32_t boff = (uint32_t)(warp_n * 64 + ng * 16 + (lid & 15)) * 128
                                + ks * 32 + (lid >> 4) * 16;
            uint32_t bF[4];
            ldsm_x4(bF, sb + 16384 + SW128(boff));
            #pragma unroll
            for (int mt = 0; mt < 2; mt++) {
                mma16816h(acc[mt * 8 + ng * 2 + 0], aF[mt], bF[0], bF[2]);
                mma16816h(acc[mt * 8 + ng * 2 + 1], aF[mt], bF[1], bF[3]);
            }
        }
    }

    float rsum[2][2] = {{0.f, 0.f}, {0.f, 0.f}};
    #pragma unroll
    for (int mt = 0; mt < 2; mt++) {
        #pragma unroll
        for (int nt = 0; nt < 8; nt++) {
            const float* c = acc[mt * 8 + nt];
            const int colL = warp_n * 64 + nt * 8 + (lid & 3) * 2;
            const int m0 = mskS[colL], m1 = mskS[colL + 1];
            float e0 = m0 ? 0.f : ex2f(c[0] * EXP_SCALE);
            float e1 = m1 ? 0.f : ex2f(c[1] * EXP_SCALE);
            float e2 = m0 ? 0.f : ex2f(c[2] * EXP_SCALE);
            float e3 = m1 ? 0.f : ex2f(c[3] * EXP_SCALE);
            rsum[mt][0] += e0 + e1;
            rsum[mt][1] += e2 + e3;
        }
    }
    #pragma unroll
    for (int off = 1; off < 4; off <<= 1) {
        #pragma unroll
        for (int mt = 0; mt < 2; mt++) {
            rsum[mt][0] += __shfl_xor_sync(0xffffffffu, rsum[mt][0], off);
            rsum[mt][1] += __shfl_xor_sync(0xffffffffu, rsum[mt][1], off);
        }
    }
    if ((lid & 3) == 0) {
        const int rbase = warp_m * 32 + (lid >> 2);
        #pragma unroll
        for (int mt = 0; mt < 2; mt++) {
            psS[warp_n * 128 + rbase + mt * 16]     = rsum[mt][0];
            psS[warp_n * 128 + rbase + mt * 16 + 8] = rsum[mt][1];
        }
    }
    __syncthreads();
    if (tid < 128) {
        g_partials[((size_t)bh * 16 + blockIdx.y) * Sn + q0 + tid]
            = psS[tid] + psS[128 + tid];
    }
}

// ---------------------------------------------------------------------------
// Kernel 2: fused. Recompute S (fp16), w = e*invl, write w once, O += w @ V.
// ---------------------------------------------------------------------------
#define F_QF 0
#define F_PH 16384
#define F_PL 32768
#define F_K(s)  (49152 + (s) * 8192)
#define F_V(s)  (65536 + (s) * 16384)        // VH +0, VL +8192
#define F_MSK 98304
#define F_INVL 100352
#define F_TOTAL 100864

__global__ void __launch_bounds__(256)
fused_kernel(const int* __restrict__ mask, float* __restrict__ W,
             float* __restrict__ O) {
    extern __shared__ char smem[];
    const uint32_t sb = smem_u32(smem);
    const int tid = threadIdx.x, lid = tid & 31, wid = tid >> 5;
    const int warp_m = wid & 3, warp_n = wid >> 2;
    const int q0 = blockIdx.x * 128, bh = blockIdx.y;
    const int b = bh >> 4;

    char*  mskC = smem + F_MSK;
    float* invl = (float*)(smem + F_INVL);

    // prologue: Q fp16 tile + K/V chunk0 (group0), chunk1 (group1)
    #pragma unroll
    for (int j = 0; j < 4; j++) {
        const int f = tid + j * 256;
        const int row = f >> 3, c16 = f & 7;
        const uint32_t sw = SW128(row * 128 + c16 * 16);
        cpa16(sb + F_QF + sw, gQf + ((size_t)bh * Sn + q0 + row) * Dn + c16 * 8);
    }
    #pragma unroll
    for (int j = 0; j < 2; j++) {
        const int f = tid + j * 256;
        const int row = f >> 3, c16 = f & 7;
        const uint32_t sw = SW128(row * 128 + c16 * 16);
        const size_t src = ((size_t)bh * Sn + row) * Dn + c16 * 8;
        cpa16(sb + F_K(0) + sw,        gKf + src);
        cpa16(sb + F_V(0) + sw,        gVH + src);
        cpa16(sb + F_V(0) + 8192 + sw, gVL + src);
    }
    CPA_COMMIT();
    #pragma unroll
    for (int j = 0; j < 2; j++) {
        const int f = tid + j * 256;
        const int row = f >> 3, c16 = f & 7;
        const uint32_t sw = SW128(row * 128 + c16 * 16);
        const size_t src = ((size_t)bh * Sn + 64 + row) * Dn + c16 * 8;
        cpa16(sb + F_K(1) + sw,        gKf + src);
        cpa16(sb + F_V(1) + sw,        gVH + src);
        cpa16(sb + F_V(1) + 8192 + sw, gVL + src);
    }
    CPA_COMMIT();

    #pragma unroll
    for (int j = 0; j < 8; j++) {
        const int i = tid + j * 256;
        mskC[i] = (char)mask[b * Sn + i];
    }
    if (tid < 128) {
        float l = 0.f;
        #pragma unroll
        for (int kt = 0; kt < 16; kt++)
            l += g_partials[((size_t)bh * 16 + kt) * Sn + q0 + tid];
        invl[tid] = 1.0f / l;
    }

    float accO[8][4];
    #pragma unroll
    for (int i = 0; i < 8; i++)
        #pragma unroll
        for (int j = 0; j < 4; j++) accO[i][j] = 0.0f;

    float* Wb = W + (size_t)bh * Sn * Sn;

    for (int it = 0; it < 32; it++) {
        const int s = it & 1;
        const int kc = it * 64;
        if (it == 31) { CPA_WAIT(0); } else { CPA_WAIT(1); }
        __syncthreads();

        // ---- QK (fp16 single): S = Q @ K_chunk^T  (128 x 64)
        float accS[8][4];
        #pragma unroll
        for (int i = 0; i < 8; i++)
            #pragma unroll
            for (int j = 0; j < 4; j++) accS[i][j] = 0.0f;

        #pragma unroll
        for (int ks = 0; ks < 4; ks++) {
            uint32_t aF[2][4];
            #pragma unroll
            for (int mt = 0; mt < 2; mt++) {
                const uint32_t off = (uint32_t)(warp_m * 32 + mt * 16 + (lid & 15)) * 128
                                   + ks * 32 + (lid >> 4) * 16;
                ldsm_x4(aF[mt], sb + F_QF + SW128(off));
            }
            #pragma unroll
            for (int ng = 0; ng < 2; ng++) {
                const uint32_t boff = (uint32_t)(warp_n * 32 + ng * 16 + (lid & 15)) * 128
                                    + ks * 32 + (lid >> 4) * 16;
                uint32_t bF[4];
                ldsm_x4(bF, sb + F_K(s) + SW128(boff));
                #pragma unroll
                for (int mt = 0; mt < 2; mt++) {
                    mma16816h(accS[mt * 4 + ng * 2 + 0], aF[mt], bF[0], bF[2]);
                    mma16816h(accS[mt * 4 + ng * 2 + 1], aF[mt], bF[1], bF[3]);
                }
            }
        }

        // ---- epilogue: e, w = e*invl, write w, split w -> PH/PL
        #pragma unroll
        for (int mt = 0; mt < 2; mt++) {
            const int rl0 = warp_m * 32 + mt * 16 + (lid >> 2);
            const int rl1 = rl0 + 8;
            const float il0 = invl[rl0], il1 = invl[rl1];
            #pragma unroll
            for (int nt = 0; nt < 4; nt++) {
                const float* c = accS[mt * 4 + nt];
                const int col = warp_n * 32 + nt * 8 + (lid & 3) * 2;
                const int kg = kc + col;
                const int m0 = mskC[kg], m1 = mskC[kg + 1];
                const float e0 = m0 ? 0.f : ex2f(c[0] * EXP_SCALE);
                const float e1 = m1 ? 0.f : ex2f(c[1] * EXP_SCALE);
                const float e2 = m0 ? 0.f : ex2f(c[2] * EXP_SCALE);
                const float e3 = m1 ? 0.f : ex2f(c[3] * EXP_SCALE);
                const float w0 = e0 * il0, w1 = e1 * il0;
                const float w2 = e2 * il1, w3 = e3 * il1;
                *(float2*)(Wb + (size_t)(q0 + rl0) * Sn + kg) = make_float2(w0, w1);
                *(float2*)(Wb + (size_t)(q0 + rl1) * Sn + kg) = make_float2(w2, w3);
                uint16_t h0, l0, h1, l1;
                cvt_split(w0, h0, l0); cvt_split(w1, h1, l1);
                const uint32_t sw0 = SW128((uint32_t)(rl0 * 128 + col * 2));
                *(uint32_t*)(smem + F_PH + sw0) = (uint32_t)h0 | ((uint32_t)h1 << 16);
                *(uint32_t*)(smem + F_PL + sw0) = (uint32_t)l0 | ((uint32_t)l1 << 16);
                cvt_split(w2, h0, l0); cvt_split(w3, h1, l1);
                const uint32_t sw1 = SW128((uint32_t)(rl1 * 128 + col * 2));
                *(uint32_t*)(smem + F_PH + sw1) = (uint32_t)h0 | ((uint32_t)h1 << 16);
                *(uint32_t*)(smem + F_PL + sw1) = (uint32_t)l0 | ((uint32_t)l1 << 16);
            }
        }
        __syncthreads();

        // ---- AV (bf16 x3): O += P @ V_chunk  (128 x 64)
        #pragma unroll
        for (int ks = 0; ks < 4; ks++) {
            uint32_t aH[2][4], aL[2][4];
            #pragma unroll
            for (int mt = 0; mt < 2; mt++) {
                const uint32_t off = (uint32_t)(warp_m * 32 + mt * 16 + (lid & 15)) * 128
                                   + ks * 32 + (lid >> 4) * 16;
                ldsm_x4(aH[mt], sb + F_PH + SW128(off));
                ldsm_x4(aL[mt], sb + F_PL + SW128(off));
            }
            #pragma unroll
            for (int ng = 0; ng < 2; ng++) {
                const uint32_t voff =
                    (uint32_t)(ks * 16 + (lid & 7) + ((lid >> 3) & 1) * 8) * 128
                    + (warp_n * 32 + ng * 16 + (lid >> 4) * 8) * 2;
                uint32_t bHf[4], bLf[4];
                ldsm_x4t(bHf, sb + F_V(s) + SW128(voff));
                ldsm_x4t(bLf, sb + F_V(s) + 8192 + SW128(voff));
                #pragma unroll
                for (int mt = 0; mt < 2; mt++) {
                    float* c0 = accO[mt * 4 + ng * 2 + 0];
                    float* c1 = accO[mt * 4 + ng * 2 + 1];
                    mma16816(c0, aH[mt], bHf[0], bHf[1]);
                    mma16816(c0, aL[mt], bHf[0], bHf[1]);
                    mma16816(c0, aH[mt], bLf[0], bLf[1]);
                    mma16816(c1, aH[mt], bHf[2], bHf[3]);
                    mma16816(c1, aL[mt], bHf[2], bHf[3]);
                    mma16816(c1, aH[mt], bLf[2], bLf[3]);
                }
            }
        }
        __syncthreads();

        if (it + 2 < 32) {
            const int kn = (it + 2) * 64;
            #pragma unroll
            for (int j = 0; j < 2; j++) {
                const int f = tid + j * 256;
                const int row = f >> 3, c16 = f & 7;
                const uint32_t sw = SW128(row * 128 + c16 * 16);
                const size_t src = ((size_t)bh * Sn + kn + row) * Dn + c16 * 8;
                cpa16(sb + F_K(s) + sw,        gKf + src);
                cpa16(sb + F_V(s) + sw,        gVH + src);
                cpa16(sb + F_V(s) + 8192 + sw, gVL + src);
            }
            CPA_COMMIT();
        }
    }

    float* Ob = O + ((size_t)bh * Sn + q0) * Dn;
    #pragma unroll
    for (int mt = 0; mt < 2; mt++) {
        #pragma unroll
        for (int nt = 0; nt < 4; nt++) {
            const float* c = accO[mt * 4 + nt];
            const int row = warp_m * 32 + mt * 16 + (lid >> 2);
            const int col = warp_n * 32 + nt * 8 + (lid & 3) * 2;
            *(float2*)(Ob + (size_t)row * Dn + col) = make_float2(c[0], c[1]);
            *(float2*)(Ob + (size_t)(row + 8) * Dn + col) = make_float2(c[2], c[3]);
        }
    }
}

// ---------------------------------------------------------------------------
extern "C" void kernel_launch(void* const* d_in, const int* in_sizes, int n_in,
                              void* d_out, int out_size) {
    const float* Q    = (const float*)d_in[0];
    const float* K    = (const float*)d_in[1];
    const float* V    = (const float*)d_in[2];
    const int*   mask = (const int*)  d_in[3];

    float* O = (float*)d_out;
    float* W = O + OSZ;

    static const int SUMS_SMEM = 32768 + 512 + 1024;

    cudaFuncSetAttribute(sums_kernel, cudaFuncAttributeMaxDynamicSharedMemorySize, SUMS_SMEM);
    cudaFuncSetAttribute(fused_kernel, cudaFuncAttributeMaxDynamicSharedMemorySize, F_TOTAL);

    {
        dim3 grid((unsigned)(OSZ / 4 / 256), 3);
        prep_kernel<<<grid, 256>>>(Q, K, V);
    }
    {
        dim3 grid(Sn / 128, Sn / 128, BHn);
        sums_kernel<<<grid, 256, SUMS_SMEM>>>(mask);
    }
    {
        dim3 grid(Sn / 128, BHn);
        fused_kernel<<<grid, 256, F_TOTAL>>>(mask, W, O);
    }
    (void)in_sizes; (void)n_in; (void)out_size;
}

// round 7
// speedup vs baseline: 3.0504x; 1.5227x over previous
#include <cuda_runtime.h>
#include <cuda_bf16.h>
#include <cuda_fp16.h>
#include <stdint.h>

#define Sn 2048
#define Dn 64
#define Hn 16
#define BHn 64

static const size_t OSZ = (size_t)BHn * Sn * Dn;
#define EXP_SCALE 0.1803368801111204f   // 0.125 * log2(e)

// scratch: partial sums (8MB) + fp16 Q/K/V (48MB)
__device__ float g_partials[BHn * 16 * Sn];
__device__ __half gQf[(size_t)BHn * Sn * Dn];
__device__ __half gKf[(size_t)BHn * Sn * Dn];
__device__ __half gVf[(size_t)BHn * Sn * Dn];

// ------------------------------------------------------------------ helpers
__device__ __forceinline__ uint32_t smem_u32(const void* p) {
    uint32_t a;
    asm("{ .reg .u64 t; cvta.to.shared.u64 t, %1; cvt.u32.u64 %0, t; }"
        : "=r"(a) : "l"(p));
    return a;
}

#define SW128(o) ((uint32_t)(o) ^ ((((uint32_t)(o)) >> 3) & 0x70))

__device__ __forceinline__ float ex2f(float x) {
    float y; asm("ex2.approx.ftz.f32 %0, %1;" : "=f"(y) : "f"(x)); return y;
}

__device__ __forceinline__ void cpa16(uint32_t dst, const void* src) {
    asm volatile("cp.async.cg.shared.global [%0], [%1], 16;"
                 :: "r"(dst), "l"(src));
}
#define CPA_COMMIT() asm volatile("cp.async.commit_group;" ::: "memory")
#define CPA_WAIT(n)  asm volatile("cp.async.wait_group %0;" :: "n"(n) : "memory")

__device__ __forceinline__ void ldsm_x4(uint32_t r[4], uint32_t addr) {
    asm volatile("ldmatrix.sync.aligned.m8n8.x4.shared.b16 {%0,%1,%2,%3}, [%4];"
                 : "=r"(r[0]), "=r"(r[1]), "=r"(r[2]), "=r"(r[3]) : "r"(addr));
}
__device__ __forceinline__ void ldsm_x4t(uint32_t r[4], uint32_t addr) {
    asm volatile("ldmatrix.sync.aligned.m8n8.x4.trans.shared.b16 {%0,%1,%2,%3}, [%4];"
                 : "=r"(r[0]), "=r"(r[1]), "=r"(r[2]), "=r"(r[3]) : "r"(addr));
}

__device__ __forceinline__ void mma16816h(float c[4], const uint32_t a[4],
                                          uint32_t b0, uint32_t b1) {
    asm volatile(
        "mma.sync.aligned.m16n8k16.row.col.f32.f16.f16.f32 "
        "{%0,%1,%2,%3}, {%4,%5,%6,%7}, {%8,%9}, {%0,%1,%2,%3};"
        : "+f"(c[0]), "+f"(c[1]), "+f"(c[2]), "+f"(c[3])
        : "r"(a[0]), "r"(a[1]), "r"(a[2]), "r"(a[3]), "r"(b0), "r"(b1));
}

__device__ __forceinline__ uint32_t pack_h2(float a, float b) {
    __half2 h = __floats2half2_rn(a, b);
    return *(uint32_t*)&h;
}

// ---------------------------------------------------------------------------
// Kernel 0: Q,K,V -> fp16.
// ---------------------------------------------------------------------------
__global__ void __launch_bounds__(256)
prep_kernel(const float* __restrict__ Q, const float* __restrict__ K,
            const float* __restrict__ V) {
    const size_t i4 = (size_t)blockIdx.x * 256 + threadIdx.x;  // float4 index
    const int y = blockIdx.y;
    const float* src = (y == 0) ? Q : (y == 1) ? K : V;
    __half* dst = (y == 0) ? gQf : (y == 1) ? gKf : gVf;
    float4 v = ((const float4*)src)[i4];
    uint2 o;
    o.x = pack_h2(v.x, v.y);
    o.y = pack_h2(v.z, v.w);
    ((uint2*)dst)[i4] = o;
}

// ---------------------------------------------------------------------------
// Kernel 1: row partial sums of e = mask ? 0 : exp(Q@K^T / 8).  fp16 QK.
// Tile 128(q) x 128(k). 256 threads = 8 warps (4x2), warp tile 32x64.
// ---------------------------------------------------------------------------
__global__ void __launch_bounds__(256)
sums_kernel(const int* __restrict__ mask) {
    extern __shared__ char smem[];
    const uint32_t sb = smem_u32(smem);
    const int tid = threadIdx.x, lid = tid & 31, wid = tid >> 5;
    const int warp_m = wid & 3, warp_n = wid >> 2;
    const int q0 = blockIdx.x * 128, k0 = blockIdx.y * 128, bh = blockIdx.z;
    const int b = bh >> 4;

    int*   mskS = (int*)(smem + 32768);
    float* psS  = (float*)(smem + 33280);

    #pragma unroll
    for (int j = 0; j < 4; j++) {
        const int f = tid + j * 256;
        const int row = f >> 3, c16 = f & 7;
        const uint32_t sw = SW128(row * 128 + c16 * 16);
        cpa16(sb + sw,         gQf + ((size_t)bh * Sn + q0 + row) * Dn + c16 * 8);
        cpa16(sb + 16384 + sw, gKf + ((size_t)bh * Sn + k0 + row) * Dn + c16 * 8);
    }
    CPA_COMMIT();
    if (tid < 128) mskS[tid] = mask[b * Sn + k0 + tid];
    CPA_WAIT(0);
    __syncthreads();

    float acc[16][4];
    #pragma unroll
    for (int i = 0; i < 16; i++)
        #pragma unroll
        for (int j = 0; j < 4; j++) acc[i][j] = 0.0f;

    #pragma unroll
    for (int ks = 0; ks < 4; ks++) {
        uint32_t aF[2][4];
        #pragma unroll
        for (int mt = 0; mt < 2; mt++) {
            const uint32_t off = (uint32_t)(warp_m * 32 + mt * 16 + (lid & 15)) * 128
                               + ks * 32 + (lid >> 4) * 16;
            ldsm_x4(aF[mt], sb + SW128(off));
        }
        #pragma unroll
        for (int ng = 0; ng < 4; ng++) {
            const uint32_t boff = (uint32_t)(warp_n * 64 + ng * 16 + (lid & 15)) * 128
                                + ks * 32 + (lid >> 4) * 16;
            uint32_t bF[4];
            ldsm_x4(bF, sb + 16384 + SW128(boff));
            #pragma unroll
            for (int mt = 0; mt < 2; mt++) {
                mma16816h(acc[mt * 8 + ng * 2 + 0], aF[mt], bF[0], bF[2]);
                mma16816h(acc[mt * 8 + ng * 2 + 1], aF[mt], bF[1], bF[3]);
            }
        }
    }

    float rsum[2][2] = {{0.f, 0.f}, {0.f, 0.f}};
    #pragma unroll
    for (int mt = 0; mt < 2; mt++) {
        #pragma unroll
        for (int nt = 0; nt < 8; nt++) {
            const float* c = acc[mt * 8 + nt];
            const int colL = warp_n * 64 + nt * 8 + (lid & 3) * 2;
            const int m0 = mskS[colL], m1 = mskS[colL + 1];
            float e0 = m0 ? 0.f : ex2f(c[0] * EXP_SCALE);
            float e1 = m1 ? 0.f : ex2f(c[1] * EXP_SCALE);
            float e2 = m0 ? 0.f : ex2f(c[2] * EXP_SCALE);
            float e3 = m1 ? 0.f : ex2f(c[3] * EXP_SCALE);
            rsum[mt][0] += e0 + e1;
            rsum[mt][1] += e2 + e3;
        }
    }
    #pragma unroll
    for (int off = 1; off < 4; off <<= 1) {
        #pragma unroll
        for (int mt = 0; mt < 2; mt++) {
            rsum[mt][0] += __shfl_xor_sync(0xffffffffu, rsum[mt][0], off);
            rsum[mt][1] += __shfl_xor_sync(0xffffffffu, rsum[mt][1], off);
        }
    }
    if ((lid & 3) == 0) {
        const int rbase = warp_m * 32 + (lid >> 2);
        #pragma unroll
        for (int mt = 0; mt < 2; mt++) {
            psS[warp_n * 128 + rbase + mt * 16]     = rsum[mt][0];
            psS[warp_n * 128 + rbase + mt * 16 + 8] = rsum[mt][1];
        }
    }
    __syncthreads();
    if (tid < 128) {
        g_partials[((size_t)bh * 16 + blockIdx.y) * Sn + q0 + tid]
            = psS[tid] + psS[128 + tid];
    }
}

// ---------------------------------------------------------------------------
// Kernel 2: fused. Recompute S (fp16), w = e*invl, write w once, O += w @ V.
// All-fp16 MMA. Double-buffered cp.async K,V. 66.5KB smem -> 2 CTAs/SM.
// ---------------------------------------------------------------------------
#define F_QF 0
#define F_PF 16384
#define F_K(s)  (32768 + (s) * 8192)
#define F_V(s)  (49152 + (s) * 8192)
#define F_MSK 65536
#define F_INVL 67584
#define F_TOTAL 68096

__global__ void __launch_bounds__(256)
fused_kernel(const int* __restrict__ mask, float* __restrict__ W,
             float* __restrict__ O) {
    extern __shared__ char smem[];
    const uint32_t sb = smem_u32(smem);
    const int tid = threadIdx.x, lid = tid & 31, wid = tid >> 5;
    const int warp_m = wid & 3, warp_n = wid >> 2;
    const int q0 = blockIdx.x * 128, bh = blockIdx.y;
    const int b = bh >> 4;

    char*  mskC = smem + F_MSK;
    float* invl = (float*)(smem + F_INVL);

    // prologue: Q tile + K/V chunk0 (group0), chunk1 (group1)
    #pragma unroll
    for (int j = 0; j < 4; j++) {
        const int f = tid + j * 256;
        const int row = f >> 3, c16 = f & 7;
        const uint32_t sw = SW128(row * 128 + c16 * 16);
        cpa16(sb + F_QF + sw, gQf + ((size_t)bh * Sn + q0 + row) * Dn + c16 * 8);
    }
    #pragma unroll
    for (int j = 0; j < 2; j++) {
        const int f = tid + j * 256;
        const int row = f >> 3, c16 = f & 7;
        const uint32_t sw = SW128(row * 128 + c16 * 16);
        const size_t src = ((size_t)bh * Sn + row) * Dn + c16 * 8;
        cpa16(sb + F_K(0) + sw, gKf + src);
        cpa16(sb + F_V(0) + sw, gVf + src);
    }
    CPA_COMMIT();
    #pragma unroll
    for (int j = 0; j < 2; j++) {
        const int f = tid + j * 256;
        const int row = f >> 3, c16 = f & 7;
        const uint32_t sw = SW128(row * 128 + c16 * 16);
        const size_t src = ((size_t)bh * Sn + 64 + row) * Dn + c16 * 8;
        cpa16(sb + F_K(1) + sw, gKf + src);
        cpa16(sb + F_V(1) + sw, gVf + src);
    }
    CPA_COMMIT();

    #pragma unroll
    for (int j = 0; j < 8; j++) {
        const int i = tid + j * 256;
        mskC[i] = (char)mask[b * Sn + i];
    }
    if (tid < 128) {
        float l = 0.f;
        #pragma unroll
        for (int kt = 0; kt < 16; kt++)
            l += g_partials[((size_t)bh * 16 + kt) * Sn + q0 + tid];
        invl[tid] = 1.0f / l;
    }

    float accO[8][4];
    #pragma unroll
    for (int i = 0; i < 8; i++)
        #pragma unroll
        for (int j = 0; j < 4; j++) accO[i][j] = 0.0f;

    float* Wb = W + (size_t)bh * Sn * Sn;

    for (int it = 0; it < 32; it++) {
        const int s = it & 1;
        const int kc = it * 64;
        if (it == 31) { CPA_WAIT(0); } else { CPA_WAIT(1); }
        __syncthreads();

        // ---- QK: S = Q @ K_chunk^T  (128 x 64)
        float accS[8][4];
        #pragma unroll
        for (int i = 0; i < 8; i++)
            #pragma unroll
            for (int j = 0; j < 4; j++) accS[i][j] = 0.0f;

        #pragma unroll
        for (int ks = 0; ks < 4; ks++) {
            uint32_t aF[2][4];
            #pragma unroll
            for (int mt = 0; mt < 2; mt++) {
                const uint32_t off = (uint32_t)(warp_m * 32 + mt * 16 + (lid & 15)) * 128
                                   + ks * 32 + (lid >> 4) * 16;
                ldsm_x4(aF[mt], sb + F_QF + SW128(off));
            }
            #pragma unroll
            for (int ng = 0; ng < 2; ng++) {
                const uint32_t boff = (uint32_t)(warp_n * 32 + ng * 16 + (lid & 15)) * 128
                                    + ks * 32 + (lid >> 4) * 16;
                uint32_t bF[4];
                ldsm_x4(bF, sb + F_K(s) + SW128(boff));
                #pragma unroll
                for (int mt = 0; mt < 2; mt++) {
                    mma16816h(accS[mt * 4 + ng * 2 + 0], aF[mt], bF[0], bF[2]);
                    mma16816h(accS[mt * 4 + ng * 2 + 1], aF[mt], bF[1], bF[3]);
                }
            }
        }

        // ---- epilogue: e, w = e*invl, write w, pack fp16 w -> PF
        #pragma unroll
        for (int mt = 0; mt < 2; mt++) {
            const int rl0 = warp_m * 32 + mt * 16 + (lid >> 2);
            const int rl1 = rl0 + 8;
            const float il0 = invl[rl0], il1 = invl[rl1];
            #pragma unroll
            for (int nt = 0; nt < 4; nt++) {
                const float* c = accS[mt * 4 + nt];
                const int col = warp_n * 32 + nt * 8 + (lid & 3) * 2;
                const int kg = kc + col;
                const int m0 = mskC[kg], m1 = mskC[kg + 1];
                const float e0 = m0 ? 0.f : ex2f(c[0] * EXP_SCALE);
                const float e1 = m1 ? 0.f : ex2f(c[1] * EXP_SCALE);
                const float e2 = m0 ? 0.f : ex2f(c[2] * EXP_SCALE);
                const float e3 = m1 ? 0.f : ex2f(c[3] * EXP_SCALE);
                const float w0 = e0 * il0, w1 = e1 * il0;
                const float w2 = e2 * il1, w3 = e3 * il1;
                *(float2*)(Wb + (size_t)(q0 + rl0) * Sn + kg) = make_float2(w0, w1);
                *(float2*)(Wb + (size_t)(q0 + rl1) * Sn + kg) = make_float2(w2, w3);
                *(uint32_t*)(smem + F_PF + SW128((uint32_t)(rl0 * 128 + col * 2)))
                    = pack_h2(w0, w1);
                *(uint32_t*)(smem + F_PF + SW128((uint32_t)(rl1 * 128 + col * 2)))
                    = pack_h2(w2, w3);
            }
        }
        __syncthreads();

        // ---- AV: O += P @ V_chunk  (128 x 64)
        #pragma unroll
        for (int ks = 0; ks < 4; ks++) {
            uint32_t aF[2][4];
            #pragma unroll
            for (int mt = 0; mt < 2; mt++) {
                const uint32_t off = (uint32_t)(warp_m * 32 + mt * 16 + (lid & 15)) * 128
                                   + ks * 32 + (lid >> 4) * 16;
                ldsm_x4(aF[mt], sb + F_PF + SW128(off));
            }
            #pragma unroll
            for (int ng = 0; ng < 2; ng++) {
                const uint32_t voff =
                    (uint32_t)(ks * 16 + (lid & 7) + ((lid >> 3) & 1) * 8) * 128
                    + (warp_n * 32 + ng * 16 + (lid >> 4) * 8) * 2;
                uint32_t bF[4];
                ldsm_x4t(bF, sb + F_V(s) + SW128(voff));
                #pragma unroll
                for (int mt = 0; mt < 2; mt++) {
                    mma16816h(accO[mt * 4 + ng * 2 + 0], aF[mt], bF[0], bF[1]);
                    mma16816h(accO[mt * 4 + ng * 2 + 1], aF[mt], bF[2], bF[3]);
                }
            }
        }
        __syncthreads();

        if (it + 2 < 32) {
            const int kn = (it + 2) * 64;
            #pragma unroll
            for (int j = 0; j < 2; j++) {
                const int f = tid + j * 256;
                const int row = f >> 3, c16 = f & 7;
                const uint32_t sw = SW128(row * 128 + c16 * 16);
                const size_t src = ((size_t)bh * Sn + kn + row) * Dn + c16 * 8;
                cpa16(sb + F_K(s) + sw, gKf + src);
                cpa16(sb + F_V(s) + sw, gVf + src);
            }
            CPA_COMMIT();
        }
    }

    float* Ob = O + ((size_t)bh * Sn + q0) * Dn;
    #pragma unroll
    for (int mt = 0; mt < 2; mt++) {
        #pragma unroll
        for (int nt = 0; nt < 4; nt++) {
            const float* c = accO[mt * 4 + nt];
            const int row = warp_m * 32 + mt * 16 + (lid >> 2);
            const int col = warp_n * 32 + nt * 8 + (lid & 3) * 2;
            *(float2*)(Ob + (size_t)row * Dn + col) = make_float2(c[0], c[1]);
            *(float2*)(Ob + (size_t)(row + 8) * Dn + col) = make_float2(c[2], c[3]);
        }
    }
}

// ---------------------------------------------------------------------------
extern "C" void kernel_launch(void* const* d_in, const int* in_sizes, int n_in,
                              void* d_out, int out_size) {
    const float* Q    = (const float*)d_in[0];
    const float* K    = (const float*)d_in[1];
    const float* V    = (const float*)d_in[2];
    const int*   mask = (const int*)  d_in[3];

    float* O = (float*)d_out;
    float* W = O + OSZ;

    static const int SUMS_SMEM = 32768 + 512 + 1024;

    cudaFuncSetAttribute(sums_kernel, cudaFuncAttributeMaxDynamicSharedMemorySize, SUMS_SMEM);
    cudaFuncSetAttribute(fused_kernel, cudaFuncAttributeMaxDynamicSharedMemorySize, F_TOTAL);

    {
        dim3 grid((unsigned)(OSZ / 4 / 256), 3);
        prep_kernel<<<grid, 256>>>(Q, K, V);
    }
    {
        dim3 grid(Sn / 128, Sn / 128, BHn);
        sums_kernel<<<grid, 256, SUMS_SMEM>>>(mask);
    }
    {
        dim3 grid(Sn / 128, BHn);
        fused_kernel<<<grid, 256, F_TOTAL>>>(mask, W, O);
    }
    (void)in_sizes; (void)n_in; (void)out_size;
}

// round 8
// speedup vs baseline: 3.2838x; 1.0765x over previous
#include <cuda_runtime.h>
#include <cuda_fp16.h>
#include <stdint.h>

#define Sn 2048
#define Dn 64
#define Hn 16
#define BHn 64

static const size_t OSZ = (size_t)BHn * Sn * Dn;
#define EXP_SCALE 0.1803368801111204f   // 0.125 * log2(e)

// scratch: fp16 Q/K/V (48MB)
__device__ __half gQf[(size_t)BHn * Sn * Dn];
__device__ __half gKf[(size_t)BHn * Sn * Dn];
__device__ __half gVf[(size_t)BHn * Sn * Dn];

// ------------------------------------------------------------------ helpers
__device__ __forceinline__ uint32_t smem_u32(const void* p) {
    uint32_t a;
    asm("{ .reg .u64 t; cvta.to.shared.u64 t, %1; cvt.u32.u64 %0, t; }"
        : "=r"(a) : "l"(p));
    return a;
}

#define SW128(o) ((uint32_t)(o) ^ ((((uint32_t)(o)) >> 3) & 0x70))

__device__ __forceinline__ float ex2f(float x) {
    float y; asm("ex2.approx.ftz.f32 %0, %1;" : "=f"(y) : "f"(x)); return y;
}

__device__ __forceinline__ void cpa16(uint32_t dst, const void* src) {
    asm volatile("cp.async.cg.shared.global [%0], [%1], 16;"
                 :: "r"(dst), "l"(src));
}
#define CPA_COMMIT() asm volatile("cp.async.commit_group;" ::: "memory")
#define CPA_WAIT(n)  asm volatile("cp.async.wait_group %0;" :: "n"(n) : "memory")

__device__ __forceinline__ void ldsm_x4(uint32_t r[4], uint32_t addr) {
    asm volatile("ldmatrix.sync.aligned.m8n8.x4.shared.b16 {%0,%1,%2,%3}, [%4];"
                 : "=r"(r[0]), "=r"(r[1]), "=r"(r[2]), "=r"(r[3]) : "r"(addr));
}
__device__ __forceinline__ void ldsm_x4t(uint32_t r[4], uint32_t addr) {
    asm volatile("ldmatrix.sync.aligned.m8n8.x4.trans.shared.b16 {%0,%1,%2,%3}, [%4];"
                 : "=r"(r[0]), "=r"(r[1]), "=r"(r[2]), "=r"(r[3]) : "r"(addr));
}

__device__ __forceinline__ void mma16816h(float c[4], const uint32_t a[4],
                                          uint32_t b0, uint32_t b1) {
    asm volatile(
        "mma.sync.aligned.m16n8k16.row.col.f32.f16.f16.f32 "
        "{%0,%1,%2,%3}, {%4,%5,%6,%7}, {%8,%9}, {%0,%1,%2,%3};"
        : "+f"(c[0]), "+f"(c[1]), "+f"(c[2]), "+f"(c[3])
        : "r"(a[0]), "r"(a[1]), "r"(a[2]), "r"(a[3]), "r"(b0), "r"(b1));
}

__device__ __forceinline__ uint32_t pack_h2(float a, float b) {
    __half2 h = __floats2half2_rn(a, b);
    return *(uint32_t*)&h;
}

__device__ __forceinline__ void stg_cs_f2(float* p, float a, float b) {
    asm volatile("st.global.cs.v2.f32 [%0], {%1, %2};"
                 :: "l"(p), "f"(a), "f"(b) : "memory");
}

// ---------------------------------------------------------------------------
// Kernel 0: Q,K,V -> fp16.
// ---------------------------------------------------------------------------
__global__ void __launch_bounds__(256)
prep_kernel(const float* __restrict__ Q, const float* __restrict__ K,
            const float* __restrict__ V) {
    const size_t i4 = (size_t)blockIdx.x * 256 + threadIdx.x;
    const int y = blockIdx.y;
    const float* src = (y == 0) ? Q : (y == 1) ? K : V;
    __half* dst = (y == 0) ? gQf : (y == 1) ? gKf : gVf;
    float4 v = ((const float4*)src)[i4];
    uint2 o;
    o.x = pack_h2(v.x, v.y);
    o.y = pack_h2(v.z, v.w);
    ((uint2*)dst)[i4] = o;
}

// ---------------------------------------------------------------------------
// Fused kernel, two sweeps per 128-q block:
//   A: stream K (128-col chunks), S = QK^T, rowsum of e  -> invl (local)
//   B: stream K,V (64-col chunks), recompute S, w = e*invl, write W once,
//      O += w @ V.
// smem: QF 0..16K | PF 16K..32K (B) | buf 32K..64K:
//   sweep A: K double-buffer 2x16KB at 32K,48K
//   sweep B: K 2x8KB at 32K,40K; V 2x8KB at 48K,56K
// msk @64K (2KB), invl @66K, ps @66.5K
// ---------------------------------------------------------------------------
#define F_QF 0
#define F_PF 16384
#define F_KA(s) (32768 + (s) * 16384)
#define F_KB(s) (32768 + (s) * 8192)
#define F_VB(s) (49152 + (s) * 8192)
#define F_MSK 65536
#define F_INVL 67584
#define F_PS 68096
#define F_TOTAL 69120

__global__ void __launch_bounds__(256, 2)
fused_kernel(const int* __restrict__ mask, float* __restrict__ W,
             float* __restrict__ O) {
    extern __shared__ char smem[];
    const uint32_t sb = smem_u32(smem);
    const int tid = threadIdx.x, lid = tid & 31, wid = tid >> 5;
    const int warp_m = wid & 3, warp_n = wid >> 2;
    const int q0 = blockIdx.x * 128, bh = blockIdx.y;
    const int b = bh >> 4;

    char*  mskC = smem + F_MSK;
    float* invl = (float*)(smem + F_INVL);
    float* psS  = (float*)(smem + F_PS);

    const size_t bhS = (size_t)bh * Sn;

    // ---------------- prologue: Q tile + sweep-A chunks 0,1 (128 cols each)
    #pragma unroll
    for (int j = 0; j < 4; j++) {
        const int f = tid + j * 256;
        const int row = f >> 3, c16 = f & 7;
        const uint32_t sw = SW128(row * 128 + c16 * 16);
        cpa16(sb + F_QF + sw, gQf + (bhS + q0 + row) * Dn + c16 * 8);
    }
    #pragma unroll
    for (int j = 0; j < 4; j++) {
        const int f = tid + j * 256;
        const int row = f >> 3, c16 = f & 7;
        const uint32_t sw = SW128(row * 128 + c16 * 16);
        cpa16(sb + F_KA(0) + sw, gKf + (bhS + row) * Dn + c16 * 8);
    }
    CPA_COMMIT();
    #pragma unroll
    for (int j = 0; j < 4; j++) {
        const int f = tid + j * 256;
        const int row = f >> 3, c16 = f & 7;
        const uint32_t sw = SW128(row * 128 + c16 * 16);
        cpa16(sb + F_KA(1) + sw, gKf + (bhS + 128 + row) * Dn + c16 * 8);
    }
    CPA_COMMIT();

    #pragma unroll
    for (int j = 0; j < 8; j++) {
        const int i = tid + j * 256;
        mskC[i] = (char)mask[b * Sn + i];
    }

    // ---------------- sweep A: row sums
    float rsum[2][2] = {{0.f, 0.f}, {0.f, 0.f}};

    for (int it = 0; it < 16; it++) {
        const int s = it & 1;
        const int kc = it * 128;
        if (it == 15) { CPA_WAIT(0); } else { CPA_WAIT(1); }
        __syncthreads();

        float acc[16][4];
        #pragma unroll
        for (int i = 0; i < 16; i++)
            #pragma unroll
            for (int j = 0; j < 4; j++) acc[i][j] = 0.0f;

        #pragma unroll
        for (int ks = 0; ks < 4; ks++) {
            uint32_t aF[2][4];
            #pragma unroll
            for (int mt = 0; mt < 2; mt++) {
                const uint32_t off = (uint32_t)(warp_m * 32 + mt * 16 + (lid & 15)) * 128
                                   + ks * 32 + (lid >> 4) * 16;
                ldsm_x4(aF[mt], sb + F_QF + SW128(off));
            }
            #pragma unroll
            for (int ng = 0; ng < 4; ng++) {
                const uint32_t boff = (uint32_t)(warp_n * 64 + ng * 16 + (lid & 15)) * 128
                                    + ks * 32 + (lid >> 4) * 16;
                uint32_t bF[4];
                ldsm_x4(bF, sb + F_KA(s) + SW128(boff));
                #pragma unroll
                for (int mt = 0; mt < 2; mt++) {
                    mma16816h(acc[mt * 8 + ng * 2 + 0], aF[mt], bF[0], bF[2]);
                    mma16816h(acc[mt * 8 + ng * 2 + 1], aF[mt], bF[1], bF[3]);
                }
            }
        }

        #pragma unroll
        for (int mt = 0; mt < 2; mt++) {
            #pragma unroll
            for (int nt = 0; nt < 8; nt++) {
                const float* c = acc[mt * 8 + nt];
                const int colL = warp_n * 64 + nt * 8 + (lid & 3) * 2;
                const int kg = kc + colL;
                const int m0 = mskC[kg], m1 = mskC[kg + 1];
                float e0 = m0 ? 0.f : ex2f(c[0] * EXP_SCALE);
                float e1 = m1 ? 0.f : ex2f(c[1] * EXP_SCALE);
                float e2 = m0 ? 0.f : ex2f(c[2] * EXP_SCALE);
                float e3 = m1 ? 0.f : ex2f(c[3] * EXP_SCALE);
                rsum[mt][0] += e0 + e1;
                rsum[mt][1] += e2 + e3;
            }
        }
        __syncthreads();   // all ldsm reads of stage s complete

        if (it + 2 < 16) {
            const int kn = (it + 2) * 128;
            #pragma unroll
            for (int j = 0; j < 4; j++) {
                const int f = tid + j * 256;
                const int row = f >> 3, c16 = f & 7;
                const uint32_t sw = SW128(row * 128 + c16 * 16);
                cpa16(sb + F_KA(s) + sw, gKf + (bhS + kn + row) * Dn + c16 * 8);
            }
            CPA_COMMIT();
        }
    }

    // reduce row sums -> invl
    #pragma unroll
    for (int off = 1; off < 4; off <<= 1) {
        #pragma unroll
        for (int mt = 0; mt < 2; mt++) {
            rsum[mt][0] += __shfl_xor_sync(0xffffffffu, rsum[mt][0], off);
            rsum[mt][1] += __shfl_xor_sync(0xffffffffu, rsum[mt][1], off);
        }
    }
    if ((lid & 3) == 0) {
        const int rbase = warp_m * 32 + (lid >> 2);
        #pragma unroll
        for (int mt = 0; mt < 2; mt++) {
            psS[warp_n * 128 + rbase + mt * 16]     = rsum[mt][0];
            psS[warp_n * 128 + rbase + mt * 16 + 8] = rsum[mt][1];
        }
    }
    __syncthreads();
    if (tid < 128) invl[tid] = 1.0f / (psS[tid] + psS[128 + tid]);

    // ---------------- prologue B: K,V chunks 0,1 (64 cols each)
    #pragma unroll
    for (int j = 0; j < 2; j++) {
        const int f = tid + j * 256;
        const int row = f >> 3, c16 = f & 7;
        const uint32_t sw = SW128(row * 128 + c16 * 16);
        const size_t src = (bhS + row) * Dn + c16 * 8;
        cpa16(sb + F_KB(0) + sw, gKf + src);
        cpa16(sb + F_VB(0) + sw, gVf + src);
    }
    CPA_COMMIT();
    #pragma unroll
    for (int j = 0; j < 2; j++) {
        const int f = tid + j * 256;
        const int row = f >> 3, c16 = f & 7;
        const uint32_t sw = SW128(row * 128 + c16 * 16);
        const size_t src = (bhS + 64 + row) * Dn + c16 * 8;
        cpa16(sb + F_KB(1) + sw, gKf + src);
        cpa16(sb + F_VB(1) + sw, gVf + src);
    }
    CPA_COMMIT();

    float accO[8][4];
    #pragma unroll
    for (int i = 0; i < 8; i++)
        #pragma unroll
        for (int j = 0; j < 4; j++) accO[i][j] = 0.0f;

    float* Wb = W + (size_t)bh * Sn * Sn;

    // ---------------- sweep B
    for (int it = 0; it < 32; it++) {
        const int s = it & 1;
        const int kc = it * 64;
        if (it == 31) { CPA_WAIT(0); } else { CPA_WAIT(1); }
        __syncthreads();

        float accS[8][4];
        #pragma unroll
        for (int i = 0; i < 8; i++)
            #pragma unroll
            for (int j = 0; j < 4; j++) accS[i][j] = 0.0f;

        #pragma unroll
        for (int ks = 0; ks < 4; ks++) {
            uint32_t aF[2][4];
            #pragma unroll
            for (int mt = 0; mt < 2; mt++) {
                const uint32_t off = (uint32_t)(warp_m * 32 + mt * 16 + (lid & 15)) * 128
                                   + ks * 32 + (lid >> 4) * 16;
                ldsm_x4(aF[mt], sb + F_QF + SW128(off));
            }
            #pragma unroll
            for (int ng = 0; ng < 2; ng++) {
                const uint32_t boff = (uint32_t)(warp_n * 32 + ng * 16 + (lid & 15)) * 128
                                    + ks * 32 + (lid >> 4) * 16;
                uint32_t bF[4];
                ldsm_x4(bF, sb + F_KB(s) + SW128(boff));
                #pragma unroll
                for (int mt = 0; mt < 2; mt++) {
                    mma16816h(accS[mt * 4 + ng * 2 + 0], aF[mt], bF[0], bF[2]);
                    mma16816h(accS[mt * 4 + ng * 2 + 1], aF[mt], bF[1], bF[3]);
                }
            }
        }

        // epilogue: e, w = e*invl, write w (streaming), pack fp16 w -> PF
        #pragma unroll
        for (int mt = 0; mt < 2; mt++) {
            const int rl0 = warp_m * 32 + mt * 16 + (lid >> 2);
            const int rl1 = rl0 + 8;
            const float il0 = invl[rl0], il1 = invl[rl1];
            #pragma unroll
            for (int nt = 0; nt < 4; nt++) {
                const float* c = accS[mt * 4 + nt];
                const int col = warp_n * 32 + nt * 8 + (lid & 3) * 2;
                const int kg = kc + col;
                const int m0 = mskC[kg], m1 = mskC[kg + 1];
                const float e0 = m0 ? 0.f : ex2f(c[0] * EXP_SCALE);
                const float e1 = m1 ? 0.f : ex2f(c[1] * EXP_SCALE);
                const float e2 = m0 ? 0.f : ex2f(c[2] * EXP_SCALE);
                const float e3 = m1 ? 0.f : ex2f(c[3] * EXP_SCALE);
                const float w0 = e0 * il0, w1 = e1 * il0;
                const float w2 = e2 * il1, w3 = e3 * il1;
                stg_cs_f2(Wb + (size_t)(q0 + rl0) * Sn + kg, w0, w1);
                stg_cs_f2(Wb + (size_t)(q0 + rl1) * Sn + kg, w2, w3);
                *(uint32_t*)(smem + F_PF + SW128((uint32_t)(rl0 * 128 + col * 2)))
                    = pack_h2(w0, w1);
                *(uint32_t*)(smem + F_PF + SW128((uint32_t)(rl1 * 128 + col * 2)))
                    = pack_h2(w2, w3);
            }
        }
        __syncthreads();

        // AV: O += P @ V_chunk
        #pragma unroll
        for (int ks = 0; ks < 4; ks++) {
            uint32_t aF[2][4];
            #pragma unroll
            for (int mt = 0; mt < 2; mt++) {
                const uint32_t off = (uint32_t)(warp_m * 32 + mt * 16 + (lid & 15)) * 128
                                   + ks * 32 + (lid >> 4) * 16;
                ldsm_x4(aF[mt], sb + F_PF + SW128(off));
            }
            #pragma unroll
            for (int ng = 0; ng < 2; ng++) {
                const uint32_t voff =
                    (uint32_t)(ks * 16 + (lid & 7) + ((lid >> 3) & 1) * 8) * 128
                    + (warp_n * 32 + ng * 16 + (lid >> 4) * 8) * 2;
                uint32_t bF[4];
                ldsm_x4t(bF, sb + F_VB(s) + SW128(voff));
                #pragma unroll
                for (int mt = 0; mt < 2; mt++) {
                    mma16816h(accO[mt * 4 + ng * 2 + 0], aF[mt], bF[0], bF[1]);
                    mma16816h(accO[mt * 4 + ng * 2 + 1], aF[mt], bF[2], bF[3]);
                }
            }
        }
        __syncthreads();

        if (it + 2 < 32) {
            const int kn = (it + 2) * 64;
            #pragma unroll
            for (int j = 0; j < 2; j++) {
                const int f = tid + j * 256;
                const int row = f >> 3, c16 = f & 7;
                const uint32_t sw = SW128(row * 128 + c16 * 16);
                const size_t src = (bhS + kn + row) * Dn + c16 * 8;
                cpa16(sb + F_KB(s) + sw, gKf + src);
                cpa16(sb + F_VB(s) + sw, gVf + src);
            }
            CPA_COMMIT();
        }
    }

    float* Ob = O + (bhS + q0) * Dn;
    #pragma unroll
    for (int mt = 0; mt < 2; mt++) {
        #pragma unroll
        for (int nt = 0; nt < 4; nt++) {
            const float* c = accO[mt * 4 + nt];
            const int row = warp_m * 32 + mt * 16 + (lid >> 2);
            const int col = warp_n * 32 + nt * 8 + (lid & 3) * 2;
            stg_cs_f2(Ob + (size_t)row * Dn + col, c[0], c[1]);
            stg_cs_f2(Ob + (size_t)(row + 8) * Dn + col, c[2], c[3]);
        }
    }
}

// ---------------------------------------------------------------------------
extern "C" void kernel_launch(void* const* d_in, const int* in_sizes, int n_in,
                              void* d_out, int out_size) {
    const float* Q    = (const float*)d_in[0];
    const float* K    = (const float*)d_in[1];
    const float* V    = (const float*)d_in[2];
    const int*   mask = (const int*)  d_in[3];

    float* O = (float*)d_out;
    float* W = O + OSZ;

    cudaFuncSetAttribute(fused_kernel, cudaFuncAttributeMaxDynamicSharedMemorySize, F_TOTAL);

    {
        dim3 grid((unsigned)(OSZ / 4 / 256), 3);
        prep_kernel<<<grid, 256>>>(Q, K, V);
    }
    {
        dim3 grid(Sn / 128, BHn);
        fused_kernel<<<grid, 256, F_TOTAL>>>(mask, W, O);
    }
    (void)in_sizes; (void)n_in; (void)out_size;
}

// round 9
// speedup vs baseline: 3.7811x; 1.1514x over previous
#include <cuda_runtime.h>
#include <cuda_fp16.h>
#include <stdint.h>

#define Sn 2048
#define Dn 64
#define Hn 16
#define BHn 64

static const size_t OSZ = (size_t)BHn * Sn * Dn;
#define EXP_SCALE 0.1803368801111204f   // 0.125 * log2(e)

__device__ __half gQf[(size_t)BHn * Sn * Dn];
__device__ __half gKf[(size_t)BHn * Sn * Dn];
__device__ __half gVf[(size_t)BHn * Sn * Dn];

// ------------------------------------------------------------------ helpers
__device__ __forceinline__ uint32_t smem_u32(const void* p) {
    uint32_t a;
    asm("{ .reg .u64 t; cvta.to.shared.u64 t, %1; cvt.u32.u64 %0, t; }"
        : "=r"(a) : "l"(p));
    return a;
}

#define SW128(o) ((uint32_t)(o) ^ ((((uint32_t)(o)) >> 3) & 0x70))

__device__ __forceinline__ float ex2f(float x) {
    float y; asm("ex2.approx.ftz.f32 %0, %1;" : "=f"(y) : "f"(x)); return y;
}

__device__ __forceinline__ void cpa16(uint32_t dst, const void* src) {
    asm volatile("cp.async.cg.shared.global [%0], [%1], 16;"
                 :: "r"(dst), "l"(src));
}
#define CPA_COMMIT() asm volatile("cp.async.commit_group;" ::: "memory")
#define CPA_WAIT(n)  asm volatile("cp.async.wait_group %0;" :: "n"(n) : "memory")

__device__ __forceinline__ void ldsm_x4(uint32_t r[4], uint32_t addr) {
    asm volatile("ldmatrix.sync.aligned.m8n8.x4.shared.b16 {%0,%1,%2,%3}, [%4];"
                 : "=r"(r[0]), "=r"(r[1]), "=r"(r[2]), "=r"(r[3]) : "r"(addr));
}
__device__ __forceinline__ void ldsm_x4t(uint32_t r[4], uint32_t addr) {
    asm volatile("ldmatrix.sync.aligned.m8n8.x4.trans.shared.b16 {%0,%1,%2,%3}, [%4];"
                 : "=r"(r[0]), "=r"(r[1]), "=r"(r[2]), "=r"(r[3]) : "r"(addr));
}

__device__ __forceinline__ void mma16816h(float c[4], const uint32_t a[4],
                                          uint32_t b0, uint32_t b1) {
    asm volatile(
        "mma.sync.aligned.m16n8k16.row.col.f32.f16.f16.f32 "
        "{%0,%1,%2,%3}, {%4,%5,%6,%7}, {%8,%9}, {%0,%1,%2,%3};"
        : "+f"(c[0]), "+f"(c[1]), "+f"(c[2]), "+f"(c[3])
        : "r"(a[0]), "r"(a[1]), "r"(a[2]), "r"(a[3]), "r"(b0), "r"(b1));
}

__device__ __forceinline__ uint32_t pack_h2(float a, float b) {
    __half2 h = __floats2half2_rn(a, b);
    return *(uint32_t*)&h;
}

__device__ __forceinline__ void stg_cs_f2(float* p, float a, float b) {
    asm volatile("st.global.cs.v2.f32 [%0], {%1, %2};"
                 :: "l"(p), "f"(a), "f"(b) : "memory");
}

// ---------------------------------------------------------------------------
// Kernel 0: Q,K,V -> fp16.
// ---------------------------------------------------------------------------
__global__ void __launch_bounds__(256)
prep_kernel(const float* __restrict__ Q, const float* __restrict__ K,
            const float* __restrict__ V) {
    const size_t i4 = (size_t)blockIdx.x * 256 + threadIdx.x;
    const int y = blockIdx.y;
    const float* src = (y == 0) ? Q : (y == 1) ? K : V;
    __half* dst = (y == 0) ? gQf : (y == 1) ? gKf : gVf;
    float4 v = ((const float4*)src)[i4];
    uint2 o;
    o.x = pack_h2(v.x, v.y);
    o.y = pack_h2(v.z, v.w);
    ((uint2*)dst)[i4] = o;
}

// ---------------------------------------------------------------------------
// Fused kernel. Sweep A: row sums (warp tile 32x64). Sweep B: warp owns 16
// q-rows x full chunk; S accumulators feed AV directly as A-fragments.
// smem: QF 16K | K stages 2x16K | V stages 2x16K | msk | invl | ps
// ---------------------------------------------------------------------------
#define F_QF 0
#define F_KB(s) (16384 + (s) * 16384)
#define F_VB(s) (49152 + (s) * 16384)
#define F_MSK 81920
#define F_INVL 84480
#define F_PS 84992
#define F_TOTAL 86016

__global__ void __launch_bounds__(256, 2)
fused_kernel(const int* __restrict__ mask, float* __restrict__ W,
             float* __restrict__ O) {
    extern __shared__ char smem[];
    const uint32_t sb = smem_u32(smem);
    const int tid = threadIdx.x, lid = tid & 31, wid = tid >> 5;
    const int q0 = blockIdx.x * 128, bh = blockIdx.y;
    const int b = bh >> 4;

    char*  mskC = smem + F_MSK;
    float* invl = (float*)(smem + F_INVL);
    float* psS  = (float*)(smem + F_PS);

    const size_t bhS = (size_t)bh * Sn;

    // ---------------- prologue: Q tile + sweep-A K chunks 0,1 (128 rows each)
    #pragma unroll
    for (int j = 0; j < 4; j++) {
        const int f = tid + j * 256;
        const int row = f >> 3, c16 = f & 7;
        const uint32_t sw = SW128(row * 128 + c16 * 16);
        cpa16(sb + F_QF + sw, gQf + (bhS + q0 + row) * Dn + c16 * 8);
    }
    #pragma unroll
    for (int j = 0; j < 4; j++) {
        const int f = tid + j * 256;
        const int row = f >> 3, c16 = f & 7;
        const uint32_t sw = SW128(row * 128 + c16 * 16);
        cpa16(sb + F_KB(0) + sw, gKf + (bhS + row) * Dn + c16 * 8);
    }
    CPA_COMMIT();
    #pragma unroll
    for (int j = 0; j < 4; j++) {
        const int f = tid + j * 256;
        const int row = f >> 3, c16 = f & 7;
        const uint32_t sw = SW128(row * 128 + c16 * 16);
        cpa16(sb + F_KB(1) + sw, gKf + (bhS + 128 + row) * Dn + c16 * 8);
    }
    CPA_COMMIT();

    #pragma unroll
    for (int j = 0; j < 8; j++) {
        const int i = tid + j * 256;
        mskC[i] = (char)mask[b * Sn + i];
    }

    CPA_WAIT(1);
    __syncthreads();   // Q + K chunk0 ready

    // ---------------- sweep A: row sums. warp tile 32(m) x 64(n).
    {
        const int warp_m = wid & 3, warp_n = wid >> 2;
        uint32_t qfA[2][4][4];
        #pragma unroll
        for (int mt = 0; mt < 2; mt++)
            #pragma unroll
            for (int ks = 0; ks < 4; ks++) {
                const uint32_t off = (uint32_t)(warp_m * 32 + mt * 16 + (lid & 15)) * 128
                                   + ks * 32 + (lid >> 4) * 16;
                ldsm_x4(qfA[mt][ks], sb + F_QF + SW128(off));
            }

        float rsum[2][2] = {{0.f, 0.f}, {0.f, 0.f}};

        for (int it = 0; it < 16; it++) {
            const int s = it & 1;
            const int kc = it * 128;
            if (it > 0) {
                if (it == 15) { CPA_WAIT(0); } else { CPA_WAIT(1); }
                __syncthreads();
            }

            #pragma unroll
            for (int ng = 0; ng < 4; ng++) {
                float acc[2][2][4];
                #pragma unroll
                for (int mt = 0; mt < 2; mt++)
                    #pragma unroll
                    for (int p = 0; p < 2; p++)
                        #pragma unroll
                        for (int j = 0; j < 4; j++) acc[mt][p][j] = 0.f;
                #pragma unroll
                for (int ks = 0; ks < 4; ks++) {
                    const uint32_t boff =
                        (uint32_t)(warp_n * 64 + ng * 16 + (lid & 15)) * 128
                        + ks * 32 + (lid >> 4) * 16;
                    uint32_t bF[4];
                    ldsm_x4(bF, sb + F_KB(s) + SW128(boff));
                    #pragma unroll
                    for (int mt = 0; mt < 2; mt++) {
                        mma16816h(acc[mt][0], qfA[mt][ks], bF[0], bF[2]);
                        mma16816h(acc[mt][1], qfA[mt][ks], bF[1], bF[3]);
                    }
                }
                #pragma unroll
                for (int mt = 0; mt < 2; mt++)
                    #pragma unroll
                    for (int p = 0; p < 2; p++) {
                        const float* c = acc[mt][p];
                        const int colL = warp_n * 64 + ng * 16 + p * 8 + (lid & 3) * 2;
                        const int kg = kc + colL;
                        const int m0 = mskC[kg], m1 = mskC[kg + 1];
                        float e0 = m0 ? 0.f : ex2f(c[0] * EXP_SCALE);
                        float e1 = m1 ? 0.f : ex2f(c[1] * EXP_SCALE);
                        float e2 = m0 ? 0.f : ex2f(c[2] * EXP_SCALE);
                        float e3 = m1 ? 0.f : ex2f(c[3] * EXP_SCALE);
                        rsum[mt][0] += e0 + e1;
                        rsum[mt][1] += e2 + e3;
                    }
            }
            __syncthreads();   // K stage s reads complete

            if (it + 2 < 16) {
                const int kn = (it + 2) * 128;
                #pragma unroll
                for (int j = 0; j < 4; j++) {
                    const int f = tid + j * 256;
                    const int row = f >> 3, c16 = f & 7;
                    const uint32_t sw = SW128(row * 128 + c16 * 16);
                    cpa16(sb + F_KB(s) + sw, gKf + (bhS + kn + row) * Dn + c16 * 8);
                }
                CPA_COMMIT();
            }
        }

        #pragma unroll
        for (int off = 1; off < 4; off <<= 1) {
            #pragma unroll
            for (int mt = 0; mt < 2; mt++) {
                rsum[mt][0] += __shfl_xor_sync(0xffffffffu, rsum[mt][0], off);
                rsum[mt][1] += __shfl_xor_sync(0xffffffffu, rsum[mt][1], off);
            }
        }
        if ((lid & 3) == 0) {
            const int rbase = warp_m * 32 + (lid >> 2);
            #pragma unroll
            for (int mt = 0; mt < 2; mt++) {
                psS[warp_n * 128 + rbase + mt * 16]     = rsum[mt][0];
                psS[warp_n * 128 + rbase + mt * 16 + 8] = rsum[mt][1];
            }
        }
    }
    __syncthreads();   // psS visible; all K reads done (safe to refill)
    if (tid < 128) invl[tid] = 1.0f / (psS[tid] + psS[128 + tid]);

    // ---------------- prologue B: K,V chunks 0,1 (128 rows each)
    #pragma unroll
    for (int j = 0; j < 4; j++) {
        const int f = tid + j * 256;
        const int row = f >> 3, c16 = f & 7;
        const uint32_t sw = SW128(row * 128 + c16 * 16);
        const size_t src = (bhS + row) * Dn + c16 * 8;
        cpa16(sb + F_KB(0) + sw, gKf + src);
        cpa16(sb + F_VB(0) + sw, gVf + src);
    }
    CPA_COMMIT();
    #pragma unroll
    for (int j = 0; j < 4; j++) {
        const int f = tid + j * 256;
        const int row = f >> 3, c16 = f & 7;
        const uint32_t sw = SW128(row * 128 + c16 * 16);
        const size_t src = (bhS + 128 + row) * Dn + c16 * 8;
        cpa16(sb + F_KB(1) + sw, gKf + src);
        cpa16(sb + F_VB(1) + sw, gVf + src);
    }
    CPA_COMMIT();

    // sweep-B Q fragments: warp owns rows wid*16 .. +16
    uint32_t qfB[4][4];
    #pragma unroll
    for (int ks = 0; ks < 4; ks++) {
        const uint32_t off = (uint32_t)(wid * 16 + (lid & 15)) * 128
                           + ks * 32 + (lid >> 4) * 16;
        ldsm_x4(qfB[ks], sb + F_QF + SW128(off));
    }

    __syncthreads();   // invl visible
    const int rA = wid * 16 + (lid >> 2);
    const int rB = rA + 8;
    const float ilA = invl[rA], ilB = invl[rB];

    float accO[8][4];
    #pragma unroll
    for (int i = 0; i < 8; i++)
        #pragma unroll
        for (int j = 0; j < 4; j++) accO[i][j] = 0.0f;

    float* Wb = W + (size_t)bh * Sn * Sn;
    float* WrA = Wb + (size_t)(q0 + rA) * Sn;
    float* WrB = Wb + (size_t)(q0 + rB) * Sn;

    CPA_WAIT(1);
    __syncthreads();   // B chunk0 ready

    // ---------------- sweep B
    for (int it = 0; it < 16; it++) {
        const int s = it & 1;
        const int kc = it * 128;
        if (it > 0) {
            if (it == 15) { CPA_WAIT(0); } else { CPA_WAIT(1); }
            __syncthreads();
        }

        #pragma unroll
        for (int h = 0; h < 2; h++) {
            // ---- S = Q @ K^T for cols kc + h*64 .. +64  (16 x 64 per warp)
            float accS[8][4];
            #pragma unroll
            for (int i = 0; i < 8; i++)
                #pragma unroll
                for (int j = 0; j < 4; j++) accS[i][j] = 0.0f;

            #pragma unroll
            for (int g = 0; g < 4; g++) {
                #pragma unroll
                for (int ks = 0; ks < 4; ks++) {
                    const uint32_t boff =
                        (uint32_t)(h * 64 + g * 16 + (lid & 15)) * 128
                        + ks * 32 + (lid >> 4) * 16;
                    uint32_t bF[4];
                    ldsm_x4(bF, sb + F_KB(s) + SW128(boff));
                    mma16816h(accS[2 * g],     qfB[ks], bF[0], bF[2]);
                    mma16816h(accS[2 * g + 1], qfB[ks], bF[1], bF[3]);
                }
            }

            // ---- epilogue: w = e*invl, stream W, pack A-fragments (regs)
            uint32_t av_a[4][4];
            #pragma unroll
            for (int t = 0; t < 8; t++) {
                const float* c = accS[t];
                const int col = h * 64 + t * 8 + (lid & 3) * 2;
                const int kg = kc + col;
                const int m0 = mskC[kg], m1 = mskC[kg + 1];
                const float e0 = m0 ? 0.f : ex2f(c[0] * EXP_SCALE);
                const float e1 = m1 ? 0.f : ex2f(c[1] * EXP_SCALE);
                const float e2 = m0 ? 0.f : ex2f(c[2] * EXP_SCALE);
                const float e3 = m1 ? 0.f : ex2f(c[3] * EXP_SCALE);
                const float w0 = e0 * ilA, w1 = e1 * ilA;
                const float w2 = e2 * ilB, w3 = e3 * ilB;
                stg_cs_f2(WrA + kg, w0, w1);
                stg_cs_f2(WrB + kg, w2, w3);
                const uint32_t pa = pack_h2(w0, w1);
                const uint32_t pb = pack_h2(w2, w3);
                if ((t & 1) == 0) { av_a[t >> 1][0] = pa; av_a[t >> 1][1] = pb; }
                else              { av_a[t >> 1][2] = pa; av_a[t >> 1][3] = pb; }
            }

            // ---- AV: O += w @ V  (16 x 64 per warp, k = 64 of this half)
            #pragma unroll
            for (int kg = 0; kg < 4; kg++) {
                #pragma unroll
                for (int dg = 0; dg < 4; dg++) {
                    const uint32_t voff =
                        (uint32_t)(h * 64 + kg * 16 + (lid & 7) + ((lid >> 3) & 1) * 8) * 128
                        + (dg * 16 + (lid >> 4) * 8) * 2;
                    uint32_t bF[4];
                    ldsm_x4t(bF, sb + F_VB(s) + SW128(voff));
                    mma16816h(accO[2 * dg],     av_a[kg], bF[0], bF[1]);
                    mma16816h(accO[2 * dg + 1], av_a[kg], bF[2], bF[3]);
                }
            }
        }
        __syncthreads();   // stage s reads complete

        if (it + 2 < 16) {
            const int kn = (it + 2) * 128;
            #pragma unroll
            for (int j = 0; j < 4; j++) {
                const int f = tid + j * 256;
                const int row = f >> 3, c16 = f & 7;
                const uint32_t sw = SW128(row * 128 + c16 * 16);
                const size_t src = (bhS + kn + row) * Dn + c16 * 8;
                cpa16(sb + F_KB(s) + sw, gKf + src);
                cpa16(sb + F_VB(s) + sw, gVf + src);
            }
            CPA_COMMIT();
        }
    }

    float* Ob = O + (bhS + q0) * Dn;
    #pragma unroll
    for (int t = 0; t < 8; t++) {
        const float* c = accO[t];
        const int col = t * 8 + (lid & 3) * 2;
        stg_cs_f2(Ob + (size_t)rA * Dn + col, c[0], c[1]);
        stg_cs_f2(Ob + (size_t)rB * Dn + col, c[2], c[3]);
    }
}

// ---------------------------------------------------------------------------
extern "C" void kernel_launch(void* const* d_in, const int* in_sizes, int n_in,
                              void* d_out, int out_size) {
    const float* Q    = (const float*)d_in[0];
    const float* K    = (const float*)d_in[1];
    const float* V    = (const float*)d_in[2];
    const int*   mask = (const int*)  d_in[3];

    float* O = (float*)d_out;
    float* W = O + OSZ;

    cudaFuncSetAttribute(fused_kernel, cudaFuncAttributeMaxDynamicSharedMemorySize, F_TOTAL);

    {
        dim3 grid((unsigned)(OSZ / 4 / 256), 3);
        prep_kernel<<<grid, 256>>>(Q, K, V);
    }
    {
        dim3 grid(Sn / 128, BHn);
        fused_kernel<<<grid, 256, F_TOTAL>>>(mask, W, O);
    }
    (void)in_sizes; (void)n_in; (void)out_size;
}